// round 11
// baseline (speedup 1.0000x reference)
#include <cuda_runtime.h>
#include <cuda_bf16.h>
#include <math.h>
#include <stdint.h>

// Problem constants
#define Bb   32
#define Tt   2048
#define Ee   256
#define Hh   256
#define NLBL 20
#define Mrows (Bb * Tt)   // 65536
#define NPART 64          // 32-row pooling partials per batch (2048/32)

// ---------------------------------------------------------------------------
// Device scratch.
// g_W2s: per (dir,jhalf), 8 slabs of [384 rows x 128 B] (SW128 within row):
//   slab c = W hi chunk c ; slab 4+c = W lo chunk c
//   row order GATE-INTERLEAVED: n = (jl>>5)*96 + gate*32 + (jl&31)
// X is converted inside the GEMM kernel (no X image in global).
// ---------------------------------------------------------------------------
__device__ __align__(128) unsigned char g_W2s[(size_t)4 * 8 * 49152];     // 1.5 MB
__device__ float g_psum[Bb * NPART * 512];
__device__ float g_pmax[Bb * NPART * 512];
__device__ float g_doc[Bb * 1024];
__device__ float g_d1[Bb * 256];

// ---------------------------------------------------------------------------
// PTX helpers
// ---------------------------------------------------------------------------
__device__ __forceinline__ uint32_t smem_u32(const void* p) {
    uint32_t a;
    asm("{ .reg .u64 t; cvta.to.shared.u64 t, %1; cvt.u32.u64 %0, t; }" : "=r"(a) : "l"(p));
    return a;
}
__device__ __forceinline__ float tanha(float x) {
    float y;
    asm("tanh.approx.f32 %0, %1;" : "=f"(y) : "f"(x));
    return y;
}

#define MBARRIER_INIT(addr, cnt) \
    asm volatile("mbarrier.init.shared.b64 [%0], %1;" :: "r"((uint32_t)(addr)), "r"((uint32_t)(cnt)) : "memory")
#define MBARRIER_INVAL(addr) \
    asm volatile("mbarrier.inval.shared.b64 [%0];" :: "r"((uint32_t)(addr)) : "memory")
#define MBARRIER_EXPECT_TX(addr, bytes) \
    asm volatile("mbarrier.arrive.expect_tx.shared.b64 _, [%0], %1;" :: "r"((uint32_t)(addr)), "r"((uint32_t)(bytes)) : "memory")

#define MBARRIER_WAIT_PARITY(mbar_smem_addr, phase_parity) do { \
    uint32_t _mbar = (uint32_t)(mbar_smem_addr); \
    uint32_t _parity = (uint32_t)(phase_parity); \
    uint32_t _done; \
    asm volatile( \
        "{\n\t.reg .pred p;\n\t" \
        "mbarrier.try_wait.parity.acquire.cta.shared::cta.b64 p, [%1], %2;\n\t" \
        "selp.b32 %0, 1, 0, p;\n\t}" \
        : "=r"(_done) : "r"(_mbar), "r"(_parity) : "memory"); \
    if (!_done) { \
        asm volatile( \
            "{\n\t.reg .pred P1;\n\t" \
            "WAIT_LOOP_%=:\n\t" \
            "mbarrier.try_wait.parity.acquire.cta.shared::cta.b64 P1, [%0], %1, 0x989680;\n\t" \
            "@P1 bra.uni WAIT_DONE_%=;\n\t" \
            "bra.uni WAIT_LOOP_%=;\n\t" \
            "WAIT_DONE_%=:\n\t}" \
            :: "r"(_mbar), "r"(_parity) : "memory"); \
    } \
} while (0)

#define CP_BULK(dst, src, sz, mbar) \
    asm volatile("cp.async.bulk.shared::cluster.global.mbarrier::complete_tx::bytes [%0], [%1], %2, [%3];" \
                 :: "r"((uint32_t)(dst)), "l"(src), "r"((uint32_t)(sz)), "r"((uint32_t)(mbar)) : "memory")

#define LDSM_X4(r0, r1, r2, r3, addr) \
    asm volatile("ldmatrix.sync.aligned.m8n8.x4.shared.b16 {%0,%1,%2,%3}, [%4];" \
                 : "=r"(r0), "=r"(r1), "=r"(r2), "=r"(r3) : "r"(addr))

#define MMA_BF16(d, a, b0, b1) \
    asm volatile("mma.sync.aligned.m16n8k16.row.col.f32.bf16.bf16.f32 " \
                 "{%0,%1,%2,%3}, {%4,%5,%6,%7}, {%8,%9}, {%0,%1,%2,%3};" \
                 : "+f"((d)[0]), "+f"((d)[1]), "+f"((d)[2]), "+f"((d)[3]) \
                 : "r"((a)[0]), "r"((a)[1]), "r"((a)[2]), "r"((a)[3]), \
                   "r"(b0), "r"(b1))

__device__ __forceinline__ uint32_t sw128(uint32_t off) {
    return off ^ ((off >> 3) & 0x70);
}

__device__ __forceinline__ uint32_t pack2(unsigned short a, unsigned short b) {
    return (uint32_t)a | ((uint32_t)b << 16);
}

// ---------------------------------------------------------------------------
// Convert W -> pre-swizzled, GATE-INTERLEAVED slab images. Grid 192 x 256.
// ---------------------------------------------------------------------------
__global__ void conv_w_kernel(const float* __restrict__ Wf, const float* __restrict__ Wr) {
    int i = blockIdx.x * 256 + threadIdx.x;   // 49152 threads
    int n = i >> 5;                            // 0..1535
    int m = i & 31;
    int dir = n / 768;
    int rem = n - dir * 768;
    int gate = rem >> 8;
    int jj = rem & 255;
    int gr = (gate == 0) ? jj : (gate == 1) ? 512 + jj : 768 + jj;
    const float* W = dir ? Wr : Wf;
    const float4* wp = reinterpret_cast<const float4*>(W + (size_t)gr * 256 + m * 8);
    float4 v0 = wp[0];
    float4 v1 = wp[1];
    float xs[8] = {v0.x, v0.y, v0.z, v0.w, v1.x, v1.y, v1.z, v1.w};
    unsigned short hi[8], lo[8];
#pragma unroll
    for (int j = 0; j < 8; j++) {
        __nv_bfloat16 h = __float2bfloat16(xs[j]);
        __nv_bfloat16 l = __float2bfloat16(xs[j] - __bfloat162float(h));
        hi[j] = __bfloat16_as_ushort(h);
        lo[j] = __bfloat16_as_ushort(l);
    }

    const int jhalf = jj >> 7;
    const int jl    = jj & 127;
    const int r3    = (jl >> 5) * 96 + gate * 32 + (jl & 31);
    const int c     = m >> 3;
    const int unit  = (m & 7) ^ (r3 & 7);
    const int img   = (dir * 2 + jhalf) * 8;

    uint4 hv = make_uint4(pack2(hi[0], hi[1]), pack2(hi[2], hi[3]),
                          pack2(hi[4], hi[5]), pack2(hi[6], hi[7]));
    uint4 lv = make_uint4(pack2(lo[0], lo[1]), pack2(lo[2], lo[3]),
                          pack2(lo[4], lo[5]), pack2(lo[6], lo[7]));
    size_t hi_base = ((size_t)(img + c) * 384 + r3) * 128 + unit * 16;
    size_t lo_base = ((size_t)(img + 4 + c) * 384 + r3) * 128 + unit * 16;
    *(uint4*)(g_W2s + hi_base) = hv;
    *(uint4*)(g_W2s + lo_base) = lv;
}

// ---------------------------------------------------------------------------
// HMMA gates-GEMM with in-kernel X conversion + register-level LSTM
// activation (tanh.approx) + fused masked pooling. 2 CTAs/SM.
// Per k-chunk c (64 k): threads convert X fp32 -> A hi/lo SMEM slabs, then
// 3 MMA stages: hi*Whi_c, lo*Whi_c, hi*Wlo_c. B double-buffered bulk copies.
// ---------------------------------------------------------------------------
#define SMA_SZ 8192         // one A slab: 64 rows * 128 B (hi at 0, lo at 8192)
#define SMB_SZ 49152        // 384 rows * 128 B
#define SMO_B  16384        // after A hi+lo
#define SMO_MB (SMO_B + 2 * SMB_SZ)     // 114688
#define SMEM_GEMM (SMO_MB + 64)          // 114752 -> 2 CTAs/SM

__global__ __launch_bounds__(256, 2) void gemm_mma_kernel(
    const float* __restrict__ X,
    const int* __restrict__ lengths,
    const float* __restrict__ bihf, const float* __restrict__ bhhf,
    const float* __restrict__ bihr, const float* __restrict__ bhhr)
{
    extern __shared__ char smem[];
    const uint32_t sb = smem_u32(smem);
    const int tid  = threadIdx.x;
    const int wid  = tid >> 5;
    const int lane = tid & 31;
    const int dir   = blockIdx.x >> 1;
    const int jhalf = blockIdx.x & 1;
    const int rb    = blockIdx.y * 64;

    const int b      = rb >> 11;
    const int tstart = rb & 2047;
    int len = lengths[b];
    if (len < 1) len = 1;
    if (len > Tt) len = Tt;

    if (tstart >= len) {   // entire tile masked out: write zero partials
        const int jj = tid & 127;
        const int rh = tid >> 7;
        const int pidx = ((b << 6) + (tstart >> 5) + rh) * 512 + dir * 256 + jhalf * 128 + jj;
        g_psum[pidx] = 0.0f;
        g_pmax[pidx] = -1e30f;
        return;
    }

    const int warpM = (wid & 1) * 32;
    const int hb    = wid >> 1;            // 32-h-col group
    const int warpN = hb * 96;
    const int imgbase = (dir * 2 + jhalf) * 8;

    if (tid == 0) {
        MBARRIER_INIT(sb + SMO_MB, 1);
        MBARRIER_INIT(sb + SMO_MB + 8, 1);
    }
    __syncthreads();

    // B load u = 0..7: even -> Whi_{u/2}, odd -> Wlo_{u/2}; buffer u&1.
    auto issue_b = [&](int u) {
        const uint32_t mb = sb + SMO_MB + ((u & 1) << 3);
        MBARRIER_EXPECT_TX(mb, SMB_SZ);
        const int slab = (u & 1) ? (4 + (u >> 1)) : (u >> 1);
        const unsigned char* bsrc = g_W2s + (size_t)(imgbase + slab) * SMB_SZ;
        CP_BULK(sb + SMO_B + (u & 1) * SMB_SZ, bsrc, SMB_SZ, mb);
    };
    if (tid == 0) { issue_b(0); issue_b(1); }

    float acc[2][12][4];
#pragma unroll
    for (int i = 0; i < 2; i++)
#pragma unroll
        for (int j = 0; j < 12; j++)
#pragma unroll
            for (int k = 0; k < 4; k++) acc[i][j][k] = 0.0f;

    const int aL_row = ((lane >> 3) & 1) * 8 + (lane & 7);
    const int aL_k   = (lane >> 4);
    const int bL_n   = (lane >> 4) * 8 + (lane & 7);
    const int bL_k   = (lane >> 3) & 1;

    // one MMA stage over a (A slab, B buffer) pair
    auto compute = [&](uint32_t sa, uint32_t sB) {
#pragma unroll
        for (int kk = 0; kk < 4; kk++) {
            uint32_t afr[2][4];
#pragma unroll
            for (int sub = 0; sub < 2; sub++) {
                int row = warpM + sub * 16 + aL_row;
                uint32_t off = sw128((uint32_t)(row * 128 + (kk * 2 + aL_k) * 16));
                LDSM_X4(afr[sub][0], afr[sub][1], afr[sub][2], afr[sub][3], sa + off);
            }
#pragma unroll
            for (int p = 0; p < 6; p++) {
                uint32_t b0, b1, b2, b3;
                int n = warpN + p * 16 + bL_n;
                uint32_t off = sw128((uint32_t)(n * 128 + (kk * 2 + bL_k) * 16));
                LDSM_X4(b0, b1, b2, b3, sB + off);
                MMA_BF16(acc[0][2 * p],     afr[0], b0, b1);
                MMA_BF16(acc[0][2 * p + 1], afr[0], b2, b3);
                MMA_BF16(acc[1][2 * p],     afr[1], b0, b1);
                MMA_BF16(acc[1][2 * p + 1], afr[1], b2, b3);
            }
        }
    };

    // A conversion coordinates: thread -> (row 0..63, quad 0..3), 16 k each.
    const int cv_row = tid >> 2;
    const int cv_q   = tid & 3;
    const float* xrow = X + (size_t)(rb + cv_row) * 256 + cv_q * 16;
    // swizzled store units for this thread's two 8-k groups
    const uint32_t st0 = (uint32_t)(cv_row * 128 + ((2 * cv_q)     ^ (cv_row & 7)) * 16);
    const uint32_t st1 = (uint32_t)(cv_row * 128 + ((2 * cv_q + 1) ^ (cv_row & 7)) * 16);

    for (int c = 0; c < 4; c++) {
        // ---- convert X chunk c -> A hi (sb+0) and A lo (sb+SMA_SZ) ----
        {
            const float4* xp = reinterpret_cast<const float4*>(xrow + c * 64);
            float4 v0 = xp[0], v1 = xp[1], v2 = xp[2], v3 = xp[3];
            float xs[16] = {v0.x, v0.y, v0.z, v0.w, v1.x, v1.y, v1.z, v1.w,
                            v2.x, v2.y, v2.z, v2.w, v3.x, v3.y, v3.z, v3.w};
            uint32_t hp[8], lp[8];
#pragma unroll
            for (int j = 0; j < 8; j++) {
                __nv_bfloat16 h0 = __float2bfloat16(xs[2 * j]);
                __nv_bfloat16 h1 = __float2bfloat16(xs[2 * j + 1]);
                __nv_bfloat16 l0 = __float2bfloat16(xs[2 * j]     - __bfloat162float(h0));
                __nv_bfloat16 l1 = __float2bfloat16(xs[2 * j + 1] - __bfloat162float(h1));
                hp[j] = pack2(__bfloat16_as_ushort(h0), __bfloat16_as_ushort(h1));
                lp[j] = pack2(__bfloat16_as_ushort(l0), __bfloat16_as_ushort(l1));
            }
            *(uint4*)(smem + st0)          = make_uint4(hp[0], hp[1], hp[2], hp[3]);
            *(uint4*)(smem + st1)          = make_uint4(hp[4], hp[5], hp[6], hp[7]);
            *(uint4*)(smem + SMA_SZ + st0) = make_uint4(lp[0], lp[1], lp[2], lp[3]);
            *(uint4*)(smem + SMA_SZ + st1) = make_uint4(lp[4], lp[5], lp[6], lp[7]);
        }
        __syncthreads();

        // ---- p0 + p1: Whi_c in buffer 0 ----
        MBARRIER_WAIT_PARITY(sb + SMO_MB, c & 1);
        compute(sb, sb + SMO_B);                      // hi * Whi
        compute(sb + SMA_SZ, sb + SMO_B);             // lo * Whi
        __syncthreads();
        if (c < 3 && tid == 0) issue_b(2 * c + 2);    // Whi_{c+1} -> buf0

        // ---- p2: Wlo_c in buffer 1 ----
        MBARRIER_WAIT_PARITY(sb + SMO_MB + 8, c & 1);
        compute(sb, sb + SMO_B + SMB_SZ);             // hi * Wlo
        __syncthreads();
        if (c < 3 && tid == 0) issue_b(2 * c + 3);    // Wlo_{c+1} -> buf1
    }

    // ---- register-level epilogue: tanh.approx activation + masked pooling ----
    {
        const float* __restrict__ bih = dir ? bihr : bihf;
        const float* __restrict__ bhh = dir ? bhhr : bhhf;
        const int g  = lane >> 2;
        const int tg = lane & 3;

        const int vrw  = len - tstart - warpM;
        const int prow = (b << 6) + (tstart >> 5) + (wid & 1);
        const int pcb  = dir * 256 + jhalf * 128 + hb * 32;

        if (vrw <= 0) {
            if (lane < 4) {
#pragma unroll
                for (int q = 0; q < 4; q++)
#pragma unroll
                    for (int c = 0; c < 2; c++) {
                        const int pc = pcb + q * 8 + 2 * tg + c;
                        g_psum[prow * 512 + pc] = 0.0f;
                        g_pmax[prow * 512 + pc] = -1e30f;
                    }
            }
        } else {
            const bool v0 = (g)      < vrw;
            const bool v1 = (g + 8)  < vrw;
            const bool v2 = (g + 16) < vrw;
            const bool v3 = (g + 24) < vrw;
#pragma unroll
            for (int q = 0; q < 4; q++) {
#pragma unroll
                for (int c = 0; c < 2; c++) {
                    const int jl = hb * 32 + q * 8 + 2 * tg + c;
                    const int j  = jhalf * 128 + jl;
                    const float Bi = bih[j]       + bhh[j];
                    const float Bg = bih[512 + j] + bhh[512 + j];
                    const float Bo = bih[768 + j] + bhh[768 + j];

                    float iv[4] = {acc[0][q][c],     acc[0][q][2 + c],
                                   acc[1][q][c],     acc[1][q][2 + c]};
                    float gv[4] = {acc[0][4 + q][c], acc[0][4 + q][2 + c],
                                   acc[1][4 + q][c], acc[1][4 + q][2 + c]};
                    float ov[4] = {acc[0][8 + q][c], acc[0][8 + q][2 + c],
                                   acc[1][8 + q][c], acc[1][8 + q][2 + c]};
                    const bool vld[4] = {v0, v1, v2, v3};

                    float s = 0.0f, m = -1e30f;
#pragma unroll
                    for (int r = 0; r < 4; r++) {
                        float si = fmaf(0.5f, tanha(0.5f * (iv[r] + Bi)), 0.5f);
                        float cs = si * tanha(gv[r] + Bg);
                        float so = fmaf(0.5f, tanha(0.5f * (ov[r] + Bo)), 0.5f);
                        float h  = so * tanha(cs);
                        if (vld[r]) { s += h; m = fmaxf(m, h); }
                    }
#pragma unroll
                    for (int off = 4; off < 32; off <<= 1) {
                        s += __shfl_xor_sync(0xFFFFFFFFu, s, off);
                        m = fmaxf(m, __shfl_xor_sync(0xFFFFFFFFu, m, off));
                    }
                    if (g == 0) {
                        const int pc = pcb + q * 8 + 2 * tg + c;
                        g_psum[prow * 512 + pc] = s;
                        g_pmax[prow * 512 + pc] = m;
                    }
                }
            }
        }
    }

    __syncthreads();
    if (tid == 0) {
        MBARRIER_INVAL(sb + SMO_MB);
        MBARRIER_INVAL(sb + SMO_MB + 8);
    }
}

// ---------------------------------------------------------------------------
// Tail kernel 1: reduce 64 partials -> doc, coalesced.
// ---------------------------------------------------------------------------
__global__ void reduce_kernel(const int* __restrict__ lengths)
{
    __shared__ float ss[8][64];
    __shared__ float sm[8][64];
    const int b    = blockIdx.y;
    const int cb   = blockIdx.x * 64;
    const int tid  = threadIdx.x;
    const int w    = tid >> 5;
    const int lane = tid & 31;

    int len = lengths[b];
    if (len < 1) len = 1;
    if (len > Tt) len = Tt;

    const float* ps = g_psum + (size_t)b * NPART * 512 + cb;
    const float* pm = g_pmax + (size_t)b * NPART * 512 + cb;

    float s0 = 0.f, s1 = 0.f, m0 = -1e30f, m1 = -1e30f;
#pragma unroll
    for (int k = 0; k < 8; k++) {
        const int p = w + k * 8;
        s0 += ps[p * 512 + lane];
        s1 += ps[p * 512 + 32 + lane];
        m0 = fmaxf(m0, pm[p * 512 + lane]);
        m1 = fmaxf(m1, pm[p * 512 + 32 + lane]);
    }
    ss[w][lane] = s0; ss[w][32 + lane] = s1;
    sm[w][lane] = m0; sm[w][32 + lane] = m1;
    __syncthreads();

    if (tid < 64) {
        float S = 0.f, M = -1e30f;
#pragma unroll
        for (int w2 = 0; w2 < 8; w2++) {
            S += ss[w2][tid];
            M = fmaxf(M, sm[w2][tid]);
        }
        g_doc[b * 1024 + cb + tid]       = fmaxf(S / (float)len, 0.0f);
        g_doc[b * 1024 + 512 + cb + tid] = fmaxf(M, 0.0f);
    }
}

// ---------------------------------------------------------------------------
// Tail kernel 2: layer 1. Grid (8, 32).
// ---------------------------------------------------------------------------
__global__ void mlp1_kernel(const float* __restrict__ W1, const float* __restrict__ b1)
{
    __shared__ float doc[1024];
    const int b   = blockIdx.y;
    const int og  = blockIdx.x;
    const int tid = threadIdx.x;
    const int wid = tid >> 5;
    const int lane = tid & 31;

    *(float4*)&doc[tid * 4] = *(const float4*)&g_doc[b * 1024 + tid * 4];
    __syncthreads();

    const int n0 = og * 32 + wid * 4;
    const float* __restrict__ w0 = W1 + (size_t)(n0 + 0) * 1024;
    const float* __restrict__ w1 = W1 + (size_t)(n0 + 1) * 1024;
    const float* __restrict__ w2 = W1 + (size_t)(n0 + 2) * 1024;
    const float* __restrict__ w3 = W1 + (size_t)(n0 + 3) * 1024;

    float s0 = 0.f, s1 = 0.f, s2 = 0.f, s3 = 0.f;
#pragma unroll
    for (int k = lane; k < 1024; k += 32) {
        const float d = doc[k];
        s0 = fmaf(w0[k], d, s0);
        s1 = fmaf(w1[k], d, s1);
        s2 = fmaf(w2[k], d, s2);
        s3 = fmaf(w3[k], d, s3);
    }
#pragma unroll
    for (int off = 16; off > 0; off >>= 1) {
        s0 += __shfl_xor_sync(0xFFFFFFFFu, s0, off);
        s1 += __shfl_xor_sync(0xFFFFFFFFu, s1, off);
        s2 += __shfl_xor_sync(0xFFFFFFFFu, s2, off);
        s3 += __shfl_xor_sync(0xFFFFFFFFu, s3, off);
    }
    if (lane == 0) {
        g_d1[b * 256 + n0 + 0] = s0 + b1[n0 + 0];
        g_d1[b * 256 + n0 + 1] = s1 + b1[n0 + 1];
        g_d1[b * 256 + n0 + 2] = s2 + b1[n0 + 2];
        g_d1[b * 256 + n0 + 3] = s3 + b1[n0 + 3];
    }
}

// ---------------------------------------------------------------------------
// Tail kernel 3: layer 2. Grid 32.
// ---------------------------------------------------------------------------
__global__ void mlp2_kernel(const float* __restrict__ W2, const float* __restrict__ b2,
                            float* __restrict__ out)
{
    __shared__ float d1s[256];
    const int b   = blockIdx.x;
    const int tid = threadIdx.x;
    const int wid = tid >> 5;
    const int lane = tid & 31;

    d1s[tid] = g_d1[b * 256 + tid];
    __syncthreads();

    for (int m = wid; m < NLBL; m += 8) {
        const float* __restrict__ w2r = W2 + m * 256;
        float s = 0.0f;
#pragma unroll
        for (int k = lane; k < 256; k += 32)
            s = fmaf(w2r[k], d1s[k], s);
#pragma unroll
        for (int off = 16; off > 0; off >>= 1)
            s += __shfl_xor_sync(0xFFFFFFFFu, s, off);
        if (lane == 0) out[b * NLBL + m] = s + b2[m];
    }
}

// ---------------------------------------------------------------------------
extern "C" void kernel_launch(void* const* d_in, const int* in_sizes, int n_in,
                              void* d_out, int out_size)
{
    const float* X    = (const float*)d_in[0];
    const int*   lens = (const int*)  d_in[1];
    const float* Wf   = (const float*)d_in[2];
    const float* bihf = (const float*)d_in[3];
    const float* bhhf = (const float*)d_in[4];
    const float* Wr   = (const float*)d_in[5];
    const float* bihr = (const float*)d_in[6];
    const float* bhhr = (const float*)d_in[7];
    const float* W1   = (const float*)d_in[8];
    const float* b1   = (const float*)d_in[9];
    const float* W2   = (const float*)d_in[10];
    const float* b2   = (const float*)d_in[11];
    float* out = (float*)d_out;

    cudaFuncSetAttribute(gemm_mma_kernel, cudaFuncAttributeMaxDynamicSharedMemorySize, SMEM_GEMM);

    conv_w_kernel<<<192, 256>>>(Wf, Wr);

    dim3 gG(4, 1024);
    gemm_mma_kernel<<<gG, 256, SMEM_GEMM>>>(X, lens, bihf, bhhf, bihr, bhhr);

    dim3 gR(8, Bb);
    reduce_kernel<<<gR, 256>>>(lens);
    dim3 gM1(8, Bb);
    mlp1_kernel<<<gM1, 256>>>(W1, b1);
    mlp2_kernel<<<Bb, 256>>>(W2, b2, out);
}

// round 12
// speedup vs baseline: 2.6475x; 2.6475x over previous
#include <cuda_runtime.h>
#include <cuda_bf16.h>
#include <math.h>
#include <stdint.h>

// Problem constants
#define Bb   32
#define Tt   2048
#define Ee   256
#define Hh   256
#define NLBL 20
#define Mrows (Bb * Tt)   // 65536
#define NPART 64          // 32-row pooling partials per batch (2048/32)

// ---------------------------------------------------------------------------
// Device scratch — pre-swizzled slab images for bulk copies (round-10 layout).
// ---------------------------------------------------------------------------
__device__ __align__(128) unsigned char g_X2s[(size_t)1024 * 8 * 8192];   // 64 MB
__device__ __align__(128) unsigned char g_W2s[(size_t)4 * 8 * 49152];     // 1.5 MB
__device__ float g_psum[Bb * NPART * 512];
__device__ float g_pmax[Bb * NPART * 512];
__device__ float g_doc[Bb * 1024];
__device__ float g_d1[Bb * 256];

// ---------------------------------------------------------------------------
// PTX helpers
// ---------------------------------------------------------------------------
__device__ __forceinline__ uint32_t smem_u32(const void* p) {
    uint32_t a;
    asm("{ .reg .u64 t; cvta.to.shared.u64 t, %1; cvt.u32.u64 %0, t; }" : "=r"(a) : "l"(p));
    return a;
}
__device__ __forceinline__ float tanha(float x) {
    float y;
    asm("tanh.approx.f32 %0, %1;" : "=f"(y) : "f"(x));
    return y;
}

#define MBARRIER_INIT(addr, cnt) \
    asm volatile("mbarrier.init.shared.b64 [%0], %1;" :: "r"((uint32_t)(addr)), "r"((uint32_t)(cnt)) : "memory")
#define MBARRIER_INVAL(addr) \
    asm volatile("mbarrier.inval.shared.b64 [%0];" :: "r"((uint32_t)(addr)) : "memory")
#define MBARRIER_EXPECT_TX(addr, bytes) \
    asm volatile("mbarrier.arrive.expect_tx.shared.b64 _, [%0], %1;" :: "r"((uint32_t)(addr)), "r"((uint32_t)(bytes)) : "memory")

#define MBARRIER_WAIT_PARITY(mbar_smem_addr, phase_parity) do { \
    uint32_t _mbar = (uint32_t)(mbar_smem_addr); \
    uint32_t _parity = (uint32_t)(phase_parity); \
    uint32_t _done; \
    asm volatile( \
        "{\n\t.reg .pred p;\n\t" \
        "mbarrier.try_wait.parity.acquire.cta.shared::cta.b64 p, [%1], %2;\n\t" \
        "selp.b32 %0, 1, 0, p;\n\t}" \
        : "=r"(_done) : "r"(_mbar), "r"(_parity) : "memory"); \
    if (!_done) { \
        asm volatile( \
            "{\n\t.reg .pred P1;\n\t" \
            "WAIT_LOOP_%=:\n\t" \
            "mbarrier.try_wait.parity.acquire.cta.shared::cta.b64 P1, [%0], %1, 0x989680;\n\t" \
            "@P1 bra.uni WAIT_DONE_%=;\n\t" \
            "bra.uni WAIT_LOOP_%=;\n\t" \
            "WAIT_DONE_%=:\n\t}" \
            :: "r"(_mbar), "r"(_parity) : "memory"); \
    } \
} while (0)

#define CP_BULK(dst, src, sz, mbar) \
    asm volatile("cp.async.bulk.shared::cluster.global.mbarrier::complete_tx::bytes [%0], [%1], %2, [%3];" \
                 :: "r"((uint32_t)(dst)), "l"(src), "r"((uint32_t)(sz)), "r"((uint32_t)(mbar)) : "memory")

#define LDSM_X4(r0, r1, r2, r3, addr) \
    asm volatile("ldmatrix.sync.aligned.m8n8.x4.shared.b16 {%0,%1,%2,%3}, [%4];" \
                 : "=r"(r0), "=r"(r1), "=r"(r2), "=r"(r3) : "r"(addr))

#define MMA_BF16(d, a, b0, b1) \
    asm volatile("mma.sync.aligned.m16n8k16.row.col.f32.bf16.bf16.f32 " \
                 "{%0,%1,%2,%3}, {%4,%5,%6,%7}, {%8,%9}, {%0,%1,%2,%3};" \
                 : "+f"((d)[0]), "+f"((d)[1]), "+f"((d)[2]), "+f"((d)[3]) \
                 : "r"((a)[0]), "r"((a)[1]), "r"((a)[2]), "r"((a)[3]), \
                   "r"(b0), "r"(b1))

__device__ __forceinline__ uint32_t sw128(uint32_t off) {
    return off ^ ((off >> 3) & 0x70);
}

__device__ __forceinline__ uint32_t pack2(unsigned short a, unsigned short b) {
    return (uint32_t)a | ((uint32_t)b << 16);
}

// ---------------------------------------------------------------------------
// Convert X -> pre-swizzled bf16 hi/lo slab images (round 10). Grid 8192x256.
// ---------------------------------------------------------------------------
__global__ void conv_x_kernel(const float* __restrict__ X, const int* __restrict__ lengths) {
    size_t i = (size_t)blockIdx.x * 256 + threadIdx.x;
    size_t row = i >> 5;
    int m = (int)(i & 31);
    int b = (int)(row >> 11);
    int t = (int)(row & 2047);
    int len = lengths[b];
    if (len < 1) len = 1;
    if (len > Tt) len = Tt;
    if (t >= len) return;

    const float4* xp = reinterpret_cast<const float4*>(X + row * 256 + m * 8);
    float4 v0 = xp[0];
    float4 v1 = xp[1];
    float xs[8] = {v0.x, v0.y, v0.z, v0.w, v1.x, v1.y, v1.z, v1.w};
    unsigned short hi[8], lo[8];
#pragma unroll
    for (int j = 0; j < 8; j++) {
        __nv_bfloat16 h = __float2bfloat16(xs[j]);
        __nv_bfloat16 l = __float2bfloat16(xs[j] - __bfloat162float(h));
        hi[j] = __bfloat16_as_ushort(h);
        lo[j] = __bfloat16_as_ushort(l);
    }

    const int tile = (int)(row >> 6);
    const int r    = (int)(row & 63);
    const int c    = m >> 3;
    const int unit = (m & 7) ^ (r & 7);

    uint4 hv = make_uint4(pack2(hi[0], hi[1]), pack2(hi[2], hi[3]),
                          pack2(hi[4], hi[5]), pack2(hi[6], hi[7]));
    uint4 lv = make_uint4(pack2(lo[0], lo[1]), pack2(lo[2], lo[3]),
                          pack2(lo[4], lo[5]), pack2(lo[6], lo[7]));
    size_t hi_base = ((size_t)(tile * 8 + 2 * c) * 64 + r) * 128 + unit * 16;
    size_t lo_base = ((size_t)(tile * 8 + 2 * c + 1) * 64 + r) * 128 + unit * 16;
    *(uint4*)(g_X2s + hi_base) = hv;
    *(uint4*)(g_X2s + lo_base) = lv;
}

// Convert W -> pre-swizzled, GATE-INTERLEAVED slab images. Grid 192 x 256.
__global__ void conv_w_kernel(const float* __restrict__ Wf, const float* __restrict__ Wr) {
    int i = blockIdx.x * 256 + threadIdx.x;
    int n = i >> 5;
    int m = i & 31;
    int dir = n / 768;
    int rem = n - dir * 768;
    int gate = rem >> 8;
    int jj = rem & 255;
    int gr = (gate == 0) ? jj : (gate == 1) ? 512 + jj : 768 + jj;
    const float* W = dir ? Wr : Wf;
    const float4* wp = reinterpret_cast<const float4*>(W + (size_t)gr * 256 + m * 8);
    float4 v0 = wp[0];
    float4 v1 = wp[1];
    float xs[8] = {v0.x, v0.y, v0.z, v0.w, v1.x, v1.y, v1.z, v1.w};
    unsigned short hi[8], lo[8];
#pragma unroll
    for (int j = 0; j < 8; j++) {
        __nv_bfloat16 h = __float2bfloat16(xs[j]);
        __nv_bfloat16 l = __float2bfloat16(xs[j] - __bfloat162float(h));
        hi[j] = __bfloat16_as_ushort(h);
        lo[j] = __bfloat16_as_ushort(l);
    }

    const int jhalf = jj >> 7;
    const int jl    = jj & 127;
    const int r3    = (jl >> 5) * 96 + gate * 32 + (jl & 31);
    const int c     = m >> 3;
    const int unit  = (m & 7) ^ (r3 & 7);
    const int img   = (dir * 2 + jhalf) * 8;

    uint4 hv = make_uint4(pack2(hi[0], hi[1]), pack2(hi[2], hi[3]),
                          pack2(hi[4], hi[5]), pack2(hi[6], hi[7]));
    uint4 lv = make_uint4(pack2(lo[0], lo[1]), pack2(lo[2], lo[3]),
                          pack2(lo[4], lo[5]), pack2(lo[6], lo[7]));
    size_t hi_base = ((size_t)(img + c) * 384 + r3) * 128 + unit * 16;
    size_t lo_base = ((size_t)(img + 4 + c) * 384 + r3) * 128 + unit * 16;
    *(uint4*)(g_W2s + hi_base) = hv;
    *(uint4*)(g_W2s + lo_base) = lv;
}

// ---------------------------------------------------------------------------
// HMMA gates-GEMM (round 10, unchanged): bulk-copied pre-swizzled images,
// tanh.approx register epilogue + fused masked pooling, 2 CTAs/SM.
// ---------------------------------------------------------------------------
#define SMA_SZ 8192
#define SMB_SZ 49152
#define SMO_B  16384
#define SMO_MB (SMO_B + 2 * SMB_SZ)
#define SMEM_GEMM (SMO_MB + 64)

__global__ __launch_bounds__(256, 2) void gemm_mma_kernel(
    const int* __restrict__ lengths,
    const float* __restrict__ bihf, const float* __restrict__ bhhf,
    const float* __restrict__ bihr, const float* __restrict__ bhhr)
{
    extern __shared__ char smem[];
    const uint32_t sb = smem_u32(smem);
    const int tid  = threadIdx.x;
    const int wid  = tid >> 5;
    const int lane = tid & 31;
    const int dir   = blockIdx.x >> 1;
    const int jhalf = blockIdx.x & 1;
    const int rb    = blockIdx.y * 64;

    const int b      = rb >> 11;
    const int tstart = rb & 2047;
    int len = lengths[b];
    if (len < 1) len = 1;
    if (len > Tt) len = Tt;

    if (tstart >= len) {
        const int jj = tid & 127;
        const int rh = tid >> 7;
        const int pidx = ((b << 6) + (tstart >> 5) + rh) * 512 + dir * 256 + jhalf * 128 + jj;
        g_psum[pidx] = 0.0f;
        g_pmax[pidx] = -1e30f;
        return;
    }

    const int warpM = (wid & 1) * 32;
    const int hb    = wid >> 1;
    const int warpN = hb * 96;

    const int tile8   = (rb >> 6) * 8;
    const int imgbase = (dir * 2 + jhalf) * 8;

    auto bload = [](int s) { return (s >= 8) || ((s & 1) == 0); };
    auto bbuff = [](int s) { return (s < 8) ? ((s >> 1) & 1) : (s & 1); };
    auto aslab = [](int s) { return (s < 8) ? s : 2 * (s - 8); };
    auto bslab = [](int s) { return (s < 8) ? (s >> 1) : 4 + (s - 8); };

    if (tid == 0) {
        MBARRIER_INIT(sb + SMO_MB, 1);
        MBARRIER_INIT(sb + SMO_MB + 8, 1);
    }
    __syncthreads();

    auto issue = [&](int s) {
        const uint32_t mb = sb + SMO_MB + ((s & 1) << 3);
        const uint32_t bytes = SMA_SZ + (bload(s) ? SMB_SZ : 0);
        MBARRIER_EXPECT_TX(mb, bytes);
        const unsigned char* asrc = g_X2s + (size_t)(tile8 + aslab(s)) * SMA_SZ;
        CP_BULK(sb + (s & 1) * SMA_SZ, asrc, SMA_SZ, mb);
        if (bload(s)) {
            const unsigned char* bsrc = g_W2s + (size_t)(imgbase + bslab(s)) * SMB_SZ;
            CP_BULK(sb + SMO_B + bbuff(s) * SMB_SZ, bsrc, SMB_SZ, mb);
        }
    };

    if (tid == 0) issue(0);

    float acc[2][12][4];
#pragma unroll
    for (int i = 0; i < 2; i++)
#pragma unroll
        for (int j = 0; j < 12; j++)
#pragma unroll
            for (int k = 0; k < 4; k++) acc[i][j][k] = 0.0f;

    const int aL_row = ((lane >> 3) & 1) * 8 + (lane & 7);
    const int aL_k   = (lane >> 4);
    const int bL_n   = (lane >> 4) * 8 + (lane & 7);
    const int bL_k   = (lane >> 3) & 1;

    for (int s = 0; s < 12; s++) {
        if (s < 11 && tid == 0) issue(s + 1);

        MBARRIER_WAIT_PARITY(sb + SMO_MB + ((s & 1) << 3), (s >> 1) & 1);

        const uint32_t sa = sb + (s & 1) * SMA_SZ;
        const uint32_t sB = sb + SMO_B + bbuff(s) * SMB_SZ;

#pragma unroll
        for (int kk = 0; kk < 4; kk++) {
            uint32_t afr[2][4];
#pragma unroll
            for (int sub = 0; sub < 2; sub++) {
                int row = warpM + sub * 16 + aL_row;
                uint32_t off = sw128((uint32_t)(row * 128 + (kk * 2 + aL_k) * 16));
                LDSM_X4(afr[sub][0], afr[sub][1], afr[sub][2], afr[sub][3], sa + off);
            }
#pragma unroll
            for (int p = 0; p < 6; p++) {
                uint32_t b0, b1, b2, b3;
                int n = warpN + p * 16 + bL_n;
                uint32_t off = sw128((uint32_t)(n * 128 + (kk * 2 + bL_k) * 16));
                LDSM_X4(b0, b1, b2, b3, sB + off);
                MMA_BF16(acc[0][2 * p],     afr[0], b0, b1);
                MMA_BF16(acc[0][2 * p + 1], afr[0], b2, b3);
                MMA_BF16(acc[1][2 * p],     afr[1], b0, b1);
                MMA_BF16(acc[1][2 * p + 1], afr[1], b2, b3);
            }
        }
        __syncthreads();
    }

    // register-level epilogue: tanh.approx activation + masked pooling
    {
        const float* __restrict__ bih = dir ? bihr : bihf;
        const float* __restrict__ bhh = dir ? bhhr : bhhf;
        const int g  = lane >> 2;
        const int tg = lane & 3;

        const int vrw  = len - tstart - warpM;
        const int prow = (b << 6) + (tstart >> 5) + (wid & 1);
        const int pcb  = dir * 256 + jhalf * 128 + hb * 32;

        if (vrw <= 0) {
            if (lane < 4) {
#pragma unroll
                for (int q = 0; q < 4; q++)
#pragma unroll
                    for (int c = 0; c < 2; c++) {
                        const int pc = pcb + q * 8 + 2 * tg + c;
                        g_psum[prow * 512 + pc] = 0.0f;
                        g_pmax[prow * 512 + pc] = -1e30f;
                    }
            }
        } else {
            const bool v0 = (g)      < vrw;
            const bool v1 = (g + 8)  < vrw;
            const bool v2 = (g + 16) < vrw;
            const bool v3 = (g + 24) < vrw;
#pragma unroll
            for (int q = 0; q < 4; q++) {
#pragma unroll
                for (int c = 0; c < 2; c++) {
                    const int jl = hb * 32 + q * 8 + 2 * tg + c;
                    const int j  = jhalf * 128 + jl;
                    const float Bi = bih[j]       + bhh[j];
                    const float Bg = bih[512 + j] + bhh[512 + j];
                    const float Bo = bih[768 + j] + bhh[768 + j];

                    float iv[4] = {acc[0][q][c],     acc[0][q][2 + c],
                                   acc[1][q][c],     acc[1][q][2 + c]};
                    float gv[4] = {acc[0][4 + q][c], acc[0][4 + q][2 + c],
                                   acc[1][4 + q][c], acc[1][4 + q][2 + c]};
                    float ov[4] = {acc[0][8 + q][c], acc[0][8 + q][2 + c],
                                   acc[1][8 + q][c], acc[1][8 + q][2 + c]};
                    const bool vld[4] = {v0, v1, v2, v3};

                    float s = 0.0f, m = -1e30f;
#pragma unroll
                    for (int r = 0; r < 4; r++) {
                        float si = fmaf(0.5f, tanha(0.5f * (iv[r] + Bi)), 0.5f);
                        float cs = si * tanha(gv[r] + Bg);
                        float so = fmaf(0.5f, tanha(0.5f * (ov[r] + Bo)), 0.5f);
                        float h  = so * tanha(cs);
                        if (vld[r]) { s += h; m = fmaxf(m, h); }
                    }
#pragma unroll
                    for (int off = 4; off < 32; off <<= 1) {
                        s += __shfl_xor_sync(0xFFFFFFFFu, s, off);
                        m = fmaxf(m, __shfl_xor_sync(0xFFFFFFFFu, m, off));
                    }
                    if (g == 0) {
                        const int pc = pcb + q * 8 + 2 * tg + c;
                        g_psum[prow * 512 + pc] = s;
                        g_pmax[prow * 512 + pc] = m;
                    }
                }
            }
        }
    }

    __syncthreads();
    if (tid == 0) {
        MBARRIER_INVAL(sb + SMO_MB);
        MBARRIER_INVAL(sb + SMO_MB + 8);
    }
}

// ---------------------------------------------------------------------------
// Tail kernel 1: reduce 64 partials -> doc, float4. Grid (2, 32).
// Thread (w = tid>>6, q = tid&63): float4 cols cb + q*4, partials p = w,w+4,...
// ---------------------------------------------------------------------------
__global__ void reduce_kernel(const int* __restrict__ lengths)
{
    __shared__ float4 ss[4][64];
    __shared__ float4 sm[4][64];
    const int b   = blockIdx.y;
    const int cb  = blockIdx.x * 256;
    const int tid = threadIdx.x;
    const int w   = tid >> 6;        // 0..3
    const int q   = tid & 63;        // float4 group

    int len = lengths[b];
    if (len < 1) len = 1;
    if (len > Tt) len = Tt;

    const float* base_s = g_psum + (size_t)b * NPART * 512 + cb + q * 4;
    const float* base_m = g_pmax + (size_t)b * NPART * 512 + cb + q * 4;

    float4 s = make_float4(0.f, 0.f, 0.f, 0.f);
    float4 m = make_float4(-1e30f, -1e30f, -1e30f, -1e30f);
#pragma unroll
    for (int p = 0; p < 16; p++) {
        const int pp = w + p * 4;
        float4 vs = *(const float4*)(base_s + (size_t)pp * 512);
        float4 vm = *(const float4*)(base_m + (size_t)pp * 512);
        s.x += vs.x; s.y += vs.y; s.z += vs.z; s.w += vs.w;
        m.x = fmaxf(m.x, vm.x); m.y = fmaxf(m.y, vm.y);
        m.z = fmaxf(m.z, vm.z); m.w = fmaxf(m.w, vm.w);
    }
    ss[w][q] = s;
    sm[w][q] = m;
    __syncthreads();

    if (tid < 64) {
        float4 S = ss[0][tid], M = sm[0][tid];
#pragma unroll
        for (int w2 = 1; w2 < 4; w2++) {
            float4 vs = ss[w2][tid], vm = sm[w2][tid];
            S.x += vs.x; S.y += vs.y; S.z += vs.z; S.w += vs.w;
            M.x = fmaxf(M.x, vm.x); M.y = fmaxf(M.y, vm.y);
            M.z = fmaxf(M.z, vm.z); M.w = fmaxf(M.w, vm.w);
        }
        const float inv = 1.0f / (float)len;
        float4 A = make_float4(fmaxf(S.x * inv, 0.f), fmaxf(S.y * inv, 0.f),
                               fmaxf(S.z * inv, 0.f), fmaxf(S.w * inv, 0.f));
        float4 B = make_float4(fmaxf(M.x, 0.f), fmaxf(M.y, 0.f),
                               fmaxf(M.z, 0.f), fmaxf(M.w, 0.f));
        *(float4*)&g_doc[b * 1024 + cb + tid * 4]       = A;
        *(float4*)&g_doc[b * 1024 + 512 + cb + tid * 4] = B;
    }
}

// ---------------------------------------------------------------------------
// Tail kernel 2: layer 1, float4 W1 loads. Grid (8, 32).
// ---------------------------------------------------------------------------
__global__ void mlp1_kernel(const float* __restrict__ W1, const float* __restrict__ b1)
{
    __shared__ float4 doc[256];
    const int b   = blockIdx.y;
    const int og  = blockIdx.x;
    const int tid = threadIdx.x;
    const int wid = tid >> 5;
    const int lane = tid & 31;

    doc[tid] = *(const float4*)&g_doc[b * 1024 + tid * 4];
    __syncthreads();

    const int n0 = og * 32 + wid * 4;
    const float4* __restrict__ w0 = (const float4*)(W1 + (size_t)(n0 + 0) * 1024);
    const float4* __restrict__ w1 = (const float4*)(W1 + (size_t)(n0 + 1) * 1024);
    const float4* __restrict__ w2 = (const float4*)(W1 + (size_t)(n0 + 2) * 1024);
    const float4* __restrict__ w3 = (const float4*)(W1 + (size_t)(n0 + 3) * 1024);

    float s0 = 0.f, s1 = 0.f, s2 = 0.f, s3 = 0.f;
#pragma unroll
    for (int k4 = lane; k4 < 256; k4 += 32) {
        const float4 d = doc[k4];
        float4 a = w0[k4];
        s0 = fmaf(a.x, d.x, fmaf(a.y, d.y, fmaf(a.z, d.z, fmaf(a.w, d.w, s0))));
        a = w1[k4];
        s1 = fmaf(a.x, d.x, fmaf(a.y, d.y, fmaf(a.z, d.z, fmaf(a.w, d.w, s1))));
        a = w2[k4];
        s2 = fmaf(a.x, d.x, fmaf(a.y, d.y, fmaf(a.z, d.z, fmaf(a.w, d.w, s2))));
        a = w3[k4];
        s3 = fmaf(a.x, d.x, fmaf(a.y, d.y, fmaf(a.z, d.z, fmaf(a.w, d.w, s3))));
    }
#pragma unroll
    for (int off = 16; off > 0; off >>= 1) {
        s0 += __shfl_xor_sync(0xFFFFFFFFu, s0, off);
        s1 += __shfl_xor_sync(0xFFFFFFFFu, s1, off);
        s2 += __shfl_xor_sync(0xFFFFFFFFu, s2, off);
        s3 += __shfl_xor_sync(0xFFFFFFFFu, s3, off);
    }
    if (lane == 0) {
        g_d1[b * 256 + n0 + 0] = s0 + b1[n0 + 0];
        g_d1[b * 256 + n0 + 1] = s1 + b1[n0 + 1];
        g_d1[b * 256 + n0 + 2] = s2 + b1[n0 + 2];
        g_d1[b * 256 + n0 + 3] = s3 + b1[n0 + 3];
    }
}

// ---------------------------------------------------------------------------
// Tail kernel 3: layer 2, float4. Grid 32.
// ---------------------------------------------------------------------------
__global__ void mlp2_kernel(const float* __restrict__ W2, const float* __restrict__ b2,
                            float* __restrict__ out)
{
    __shared__ float4 d1s[64];
    const int b   = blockIdx.x;
    const int tid = threadIdx.x;
    const int wid = tid >> 5;
    const int lane = tid & 31;

    if (tid < 64) d1s[tid] = *(const float4*)&g_d1[b * 256 + tid * 4];
    __syncthreads();

    for (int m = wid; m < NLBL; m += 8) {
        const float4* __restrict__ w2r = (const float4*)(W2 + m * 256);
        float s = 0.0f;
#pragma unroll
        for (int k4 = lane; k4 < 64; k4 += 32) {
            const float4 d = d1s[k4];
            const float4 a = w2r[k4];
            s = fmaf(a.x, d.x, fmaf(a.y, d.y, fmaf(a.z, d.z, fmaf(a.w, d.w, s))));
        }
#pragma unroll
        for (int off = 16; off > 0; off >>= 1)
            s += __shfl_xor_sync(0xFFFFFFFFu, s, off);
        if (lane == 0) out[b * NLBL + m] = s + b2[m];
    }
}

// ---------------------------------------------------------------------------
extern "C" void kernel_launch(void* const* d_in, const int* in_sizes, int n_in,
                              void* d_out, int out_size)
{
    const float* X    = (const float*)d_in[0];
    const int*   lens = (const int*)  d_in[1];
    const float* Wf   = (const float*)d_in[2];
    const float* bihf = (const float*)d_in[3];
    const float* bhhf = (const float*)d_in[4];
    const float* Wr   = (const float*)d_in[5];
    const float* bihr = (const float*)d_in[6];
    const float* bhhr = (const float*)d_in[7];
    const float* W1   = (const float*)d_in[8];
    const float* b1   = (const float*)d_in[9];
    const float* W2   = (const float*)d_in[10];
    const float* b2   = (const float*)d_in[11];
    float* out = (float*)d_out;

    cudaFuncSetAttribute(gemm_mma_kernel, cudaFuncAttributeMaxDynamicSharedMemorySize, SMEM_GEMM);

    conv_x_kernel<<<8192, 256>>>(X, lens);
    conv_w_kernel<<<192, 256>>>(Wf, Wr);

    dim3 gG(4, 1024);
    gemm_mma_kernel<<<gG, 256, SMEM_GEMM>>>(lens, bihf, bhhf, bihr, bhhr);

    dim3 gR(2, Bb);
    reduce_kernel<<<gR, 256>>>(lens);
    dim3 gM1(8, Bb);
    mlp1_kernel<<<gM1, 256>>>(W1, b1);
    mlp2_kernel<<<Bb, 256>>>(W2, b2, out);
}

// round 13
// speedup vs baseline: 2.6708x; 1.0088x over previous
#include <cuda_runtime.h>
#include <cuda_bf16.h>
#include <math.h>
#include <stdint.h>

// Problem constants
#define Bb   32
#define Tt   2048
#define Ee   256
#define Hh   256
#define NLBL 20
#define Mrows (Bb * Tt)   // 65536
#define NPART 64          // 32-row pooling partials per batch (2048/32)

// ---------------------------------------------------------------------------
// Device scratch — pre-swizzled slab images for bulk copies (round-10 layout).
// ---------------------------------------------------------------------------
__device__ __align__(128) unsigned char g_X2s[(size_t)1024 * 8 * 8192];   // 64 MB
__device__ __align__(128) unsigned char g_W2s[(size_t)4 * 8 * 49152];     // 1.5 MB
__device__ float g_psum[Bb * NPART * 512];
__device__ float g_pmax[Bb * NPART * 512];
__device__ float g_doc[Bb * 1024];
__device__ float g_d1[Bb * 256];

// ---------------------------------------------------------------------------
// PTX helpers
// ---------------------------------------------------------------------------
__device__ __forceinline__ uint32_t smem_u32(const void* p) {
    uint32_t a;
    asm("{ .reg .u64 t; cvta.to.shared.u64 t, %1; cvt.u32.u64 %0, t; }" : "=r"(a) : "l"(p));
    return a;
}
__device__ __forceinline__ float tanha(float x) {
    float y;
    asm("tanh.approx.f32 %0, %1;" : "=f"(y) : "f"(x));
    return y;
}

#define MBARRIER_INIT(addr, cnt) \
    asm volatile("mbarrier.init.shared.b64 [%0], %1;" :: "r"((uint32_t)(addr)), "r"((uint32_t)(cnt)) : "memory")
#define MBARRIER_INVAL(addr) \
    asm volatile("mbarrier.inval.shared.b64 [%0];" :: "r"((uint32_t)(addr)) : "memory")
#define MBARRIER_EXPECT_TX(addr, bytes) \
    asm volatile("mbarrier.arrive.expect_tx.shared.b64 _, [%0], %1;" :: "r"((uint32_t)(addr)), "r"((uint32_t)(bytes)) : "memory")

#define MBARRIER_WAIT_PARITY(mbar_smem_addr, phase_parity) do { \
    uint32_t _mbar = (uint32_t)(mbar_smem_addr); \
    uint32_t _parity = (uint32_t)(phase_parity); \
    uint32_t _done; \
    asm volatile( \
        "{\n\t.reg .pred p;\n\t" \
        "mbarrier.try_wait.parity.acquire.cta.shared::cta.b64 p, [%1], %2;\n\t" \
        "selp.b32 %0, 1, 0, p;\n\t}" \
        : "=r"(_done) : "r"(_mbar), "r"(_parity) : "memory"); \
    if (!_done) { \
        asm volatile( \
            "{\n\t.reg .pred P1;\n\t" \
            "WAIT_LOOP_%=:\n\t" \
            "mbarrier.try_wait.parity.acquire.cta.shared::cta.b64 P1, [%0], %1, 0x989680;\n\t" \
            "@P1 bra.uni WAIT_DONE_%=;\n\t" \
            "bra.uni WAIT_LOOP_%=;\n\t" \
            "WAIT_DONE_%=:\n\t}" \
            :: "r"(_mbar), "r"(_parity) : "memory"); \
    } \
} while (0)

#define CP_BULK(dst, src, sz, mbar) \
    asm volatile("cp.async.bulk.shared::cluster.global.mbarrier::complete_tx::bytes [%0], [%1], %2, [%3];" \
                 :: "r"((uint32_t)(dst)), "l"(src), "r"((uint32_t)(sz)), "r"((uint32_t)(mbar)) : "memory")

#define LDSM_X4(r0, r1, r2, r3, addr) \
    asm volatile("ldmatrix.sync.aligned.m8n8.x4.shared.b16 {%0,%1,%2,%3}, [%4];" \
                 : "=r"(r0), "=r"(r1), "=r"(r2), "=r"(r3) : "r"(addr))

#define MMA_BF16(d, a, b0, b1) \
    asm volatile("mma.sync.aligned.m16n8k16.row.col.f32.bf16.bf16.f32 " \
                 "{%0,%1,%2,%3}, {%4,%5,%6,%7}, {%8,%9}, {%0,%1,%2,%3};" \
                 : "+f"((d)[0]), "+f"((d)[1]), "+f"((d)[2]), "+f"((d)[3]) \
                 : "r"((a)[0]), "r"((a)[1]), "r"((a)[2]), "r"((a)[3]), \
                   "r"(b0), "r"(b1))

__device__ __forceinline__ uint32_t sw128(uint32_t off) {
    return off ^ ((off >> 3) & 0x70);
}

__device__ __forceinline__ uint32_t pack2(unsigned short a, unsigned short b) {
    return (uint32_t)a | ((uint32_t)b << 16);
}

// ---------------------------------------------------------------------------
// Convert X -> pre-swizzled bf16 hi/lo slab images (skip masked rows).
// ---------------------------------------------------------------------------
__global__ void conv_x_kernel(const float* __restrict__ X, const int* __restrict__ lengths) {
    size_t i = (size_t)blockIdx.x * 256 + threadIdx.x;
    size_t row = i >> 5;
    int m = (int)(i & 31);
    int b = (int)(row >> 11);
    int t = (int)(row & 2047);
    int len = lengths[b];
    if (len < 1) len = 1;
    if (len > Tt) len = Tt;
    if (t >= len) return;

    const float4* xp = reinterpret_cast<const float4*>(X + row * 256 + m * 8);
    float4 v0 = xp[0];
    float4 v1 = xp[1];
    float xs[8] = {v0.x, v0.y, v0.z, v0.w, v1.x, v1.y, v1.z, v1.w};
    unsigned short hi[8], lo[8];
#pragma unroll
    for (int j = 0; j < 8; j++) {
        __nv_bfloat16 h = __float2bfloat16(xs[j]);
        __nv_bfloat16 l = __float2bfloat16(xs[j] - __bfloat162float(h));
        hi[j] = __bfloat16_as_ushort(h);
        lo[j] = __bfloat16_as_ushort(l);
    }

    const int tile = (int)(row >> 6);
    const int r    = (int)(row & 63);
    const int c    = m >> 3;
    const int unit = (m & 7) ^ (r & 7);

    uint4 hv = make_uint4(pack2(hi[0], hi[1]), pack2(hi[2], hi[3]),
                          pack2(hi[4], hi[5]), pack2(hi[6], hi[7]));
    uint4 lv = make_uint4(pack2(lo[0], lo[1]), pack2(lo[2], lo[3]),
                          pack2(lo[4], lo[5]), pack2(lo[6], lo[7]));
    size_t hi_base = ((size_t)(tile * 8 + 2 * c) * 64 + r) * 128 + unit * 16;
    size_t lo_base = ((size_t)(tile * 8 + 2 * c + 1) * 64 + r) * 128 + unit * 16;
    *(uint4*)(g_X2s + hi_base) = hv;
    *(uint4*)(g_X2s + lo_base) = lv;
}

// Convert W -> pre-swizzled, GATE-INTERLEAVED slab images. Grid 192 x 256.
__global__ void conv_w_kernel(const float* __restrict__ Wf, const float* __restrict__ Wr) {
    int i = blockIdx.x * 256 + threadIdx.x;
    int n = i >> 5;
    int m = i & 31;
    int dir = n / 768;
    int rem = n - dir * 768;
    int gate = rem >> 8;
    int jj = rem & 255;
    int gr = (gate == 0) ? jj : (gate == 1) ? 512 + jj : 768 + jj;
    const float* W = dir ? Wr : Wf;
    const float4* wp = reinterpret_cast<const float4*>(W + (size_t)gr * 256 + m * 8);
    float4 v0 = wp[0];
    float4 v1 = wp[1];
    float xs[8] = {v0.x, v0.y, v0.z, v0.w, v1.x, v1.y, v1.z, v1.w};
    unsigned short hi[8], lo[8];
#pragma unroll
    for (int j = 0; j < 8; j++) {
        __nv_bfloat16 h = __float2bfloat16(xs[j]);
        __nv_bfloat16 l = __float2bfloat16(xs[j] - __bfloat162float(h));
        hi[j] = __bfloat16_as_ushort(h);
        lo[j] = __bfloat16_as_ushort(l);
    }

    const int jhalf = jj >> 7;
    const int jl    = jj & 127;
    const int r3    = (jl >> 5) * 96 + gate * 32 + (jl & 31);
    const int c     = m >> 3;
    const int unit  = (m & 7) ^ (r3 & 7);
    const int img   = (dir * 2 + jhalf) * 8;

    uint4 hv = make_uint4(pack2(hi[0], hi[1]), pack2(hi[2], hi[3]),
                          pack2(hi[4], hi[5]), pack2(hi[6], hi[7]));
    uint4 lv = make_uint4(pack2(lo[0], lo[1]), pack2(lo[2], lo[3]),
                          pack2(lo[4], lo[5]), pack2(lo[6], lo[7]));
    size_t hi_base = ((size_t)(img + c) * 384 + r3) * 128 + unit * 16;
    size_t lo_base = ((size_t)(img + 4 + c) * 384 + r3) * 128 + unit * 16;
    *(uint4*)(g_W2s + hi_base) = hv;
    *(uint4*)(g_W2s + lo_base) = lv;
}

// ---------------------------------------------------------------------------
// HMMA gates-GEMM (round 10, unchanged): bulk-copied pre-swizzled images,
// tanh.approx register epilogue + fused masked pooling, 2 CTAs/SM.
// ---------------------------------------------------------------------------
#define SMA_SZ 8192
#define SMB_SZ 49152
#define SMO_B  16384
#define SMO_MB (SMO_B + 2 * SMB_SZ)
#define SMEM_GEMM (SMO_MB + 64)

__global__ __launch_bounds__(256, 2) void gemm_mma_kernel(
    const int* __restrict__ lengths,
    const float* __restrict__ bihf, const float* __restrict__ bhhf,
    const float* __restrict__ bihr, const float* __restrict__ bhhr)
{
    extern __shared__ char smem[];
    const uint32_t sb = smem_u32(smem);
    const int tid  = threadIdx.x;
    const int wid  = tid >> 5;
    const int lane = tid & 31;
    const int dir   = blockIdx.x >> 1;
    const int jhalf = blockIdx.x & 1;
    const int rb    = blockIdx.y * 64;

    const int b      = rb >> 11;
    const int tstart = rb & 2047;
    int len = lengths[b];
    if (len < 1) len = 1;
    if (len > Tt) len = Tt;

    if (tstart >= len) {
        const int jj = tid & 127;
        const int rh = tid >> 7;
        const int pidx = ((b << 6) + (tstart >> 5) + rh) * 512 + dir * 256 + jhalf * 128 + jj;
        g_psum[pidx] = 0.0f;
        g_pmax[pidx] = -1e30f;
        return;
    }

    const int warpM = (wid & 1) * 32;
    const int hb    = wid >> 1;
    const int warpN = hb * 96;

    const int tile8   = (rb >> 6) * 8;
    const int imgbase = (dir * 2 + jhalf) * 8;

    auto bload = [](int s) { return (s >= 8) || ((s & 1) == 0); };
    auto bbuff = [](int s) { return (s < 8) ? ((s >> 1) & 1) : (s & 1); };
    auto aslab = [](int s) { return (s < 8) ? s : 2 * (s - 8); };
    auto bslab = [](int s) { return (s < 8) ? (s >> 1) : 4 + (s - 8); };

    if (tid == 0) {
        MBARRIER_INIT(sb + SMO_MB, 1);
        MBARRIER_INIT(sb + SMO_MB + 8, 1);
    }
    __syncthreads();

    auto issue = [&](int s) {
        const uint32_t mb = sb + SMO_MB + ((s & 1) << 3);
        const uint32_t bytes = SMA_SZ + (bload(s) ? SMB_SZ : 0);
        MBARRIER_EXPECT_TX(mb, bytes);
        const unsigned char* asrc = g_X2s + (size_t)(tile8 + aslab(s)) * SMA_SZ;
        CP_BULK(sb + (s & 1) * SMA_SZ, asrc, SMA_SZ, mb);
        if (bload(s)) {
            const unsigned char* bsrc = g_W2s + (size_t)(imgbase + bslab(s)) * SMB_SZ;
            CP_BULK(sb + SMO_B + bbuff(s) * SMB_SZ, bsrc, SMB_SZ, mb);
        }
    };

    if (tid == 0) issue(0);

    float acc[2][12][4];
#pragma unroll
    for (int i = 0; i < 2; i++)
#pragma unroll
        for (int j = 0; j < 12; j++)
#pragma unroll
            for (int k = 0; k < 4; k++) acc[i][j][k] = 0.0f;

    const int aL_row = ((lane >> 3) & 1) * 8 + (lane & 7);
    const int aL_k   = (lane >> 4);
    const int bL_n   = (lane >> 4) * 8 + (lane & 7);
    const int bL_k   = (lane >> 3) & 1;

    for (int s = 0; s < 12; s++) {
        if (s < 11 && tid == 0) issue(s + 1);

        MBARRIER_WAIT_PARITY(sb + SMO_MB + ((s & 1) << 3), (s >> 1) & 1);

        const uint32_t sa = sb + (s & 1) * SMA_SZ;
        const uint32_t sB = sb + SMO_B + bbuff(s) * SMB_SZ;

#pragma unroll
        for (int kk = 0; kk < 4; kk++) {
            uint32_t afr[2][4];
#pragma unroll
            for (int sub = 0; sub < 2; sub++) {
                int row = warpM + sub * 16 + aL_row;
                uint32_t off = sw128((uint32_t)(row * 128 + (kk * 2 + aL_k) * 16));
                LDSM_X4(afr[sub][0], afr[sub][1], afr[sub][2], afr[sub][3], sa + off);
            }
#pragma unroll
            for (int p = 0; p < 6; p++) {
                uint32_t b0, b1, b2, b3;
                int n = warpN + p * 16 + bL_n;
                uint32_t off = sw128((uint32_t)(n * 128 + (kk * 2 + bL_k) * 16));
                LDSM_X4(b0, b1, b2, b3, sB + off);
                MMA_BF16(acc[0][2 * p],     afr[0], b0, b1);
                MMA_BF16(acc[0][2 * p + 1], afr[0], b2, b3);
                MMA_BF16(acc[1][2 * p],     afr[1], b0, b1);
                MMA_BF16(acc[1][2 * p + 1], afr[1], b2, b3);
            }
        }
        __syncthreads();
    }

    // register-level epilogue: tanh.approx activation + masked pooling
    {
        const float* __restrict__ bih = dir ? bihr : bihf;
        const float* __restrict__ bhh = dir ? bhhr : bhhf;
        const int g  = lane >> 2;
        const int tg = lane & 3;

        const int vrw  = len - tstart - warpM;
        const int prow = (b << 6) + (tstart >> 5) + (wid & 1);
        const int pcb  = dir * 256 + jhalf * 128 + hb * 32;

        if (vrw <= 0) {
            if (lane < 4) {
#pragma unroll
                for (int q = 0; q < 4; q++)
#pragma unroll
                    for (int c = 0; c < 2; c++) {
                        const int pc = pcb + q * 8 + 2 * tg + c;
                        g_psum[prow * 512 + pc] = 0.0f;
                        g_pmax[prow * 512 + pc] = -1e30f;
                    }
            }
        } else {
            const bool v0 = (g)      < vrw;
            const bool v1 = (g + 8)  < vrw;
            const bool v2 = (g + 16) < vrw;
            const bool v3 = (g + 24) < vrw;
#pragma unroll
            for (int q = 0; q < 4; q++) {
#pragma unroll
                for (int c = 0; c < 2; c++) {
                    const int jl = hb * 32 + q * 8 + 2 * tg + c;
                    const int j  = jhalf * 128 + jl;
                    const float Bi = bih[j]       + bhh[j];
                    const float Bg = bih[512 + j] + bhh[512 + j];
                    const float Bo = bih[768 + j] + bhh[768 + j];

                    float iv[4] = {acc[0][q][c],     acc[0][q][2 + c],
                                   acc[1][q][c],     acc[1][q][2 + c]};
                    float gv[4] = {acc[0][4 + q][c], acc[0][4 + q][2 + c],
                                   acc[1][4 + q][c], acc[1][4 + q][2 + c]};
                    float ov[4] = {acc[0][8 + q][c], acc[0][8 + q][2 + c],
                                   acc[1][8 + q][c], acc[1][8 + q][2 + c]};
                    const bool vld[4] = {v0, v1, v2, v3};

                    float s = 0.0f, m = -1e30f;
#pragma unroll
                    for (int r = 0; r < 4; r++) {
                        float si = fmaf(0.5f, tanha(0.5f * (iv[r] + Bi)), 0.5f);
                        float cs = si * tanha(gv[r] + Bg);
                        float so = fmaf(0.5f, tanha(0.5f * (ov[r] + Bo)), 0.5f);
                        float h  = so * tanha(cs);
                        if (vld[r]) { s += h; m = fmaxf(m, h); }
                    }
#pragma unroll
                    for (int off = 4; off < 32; off <<= 1) {
                        s += __shfl_xor_sync(0xFFFFFFFFu, s, off);
                        m = fmaxf(m, __shfl_xor_sync(0xFFFFFFFFu, m, off));
                    }
                    if (g == 0) {
                        const int pc = pcb + q * 8 + 2 * tg + c;
                        g_psum[prow * 512 + pc] = s;
                        g_pmax[prow * 512 + pc] = m;
                    }
                }
            }
        }
    }

    __syncthreads();
    if (tid == 0) {
        MBARRIER_INVAL(sb + SMO_MB);
        MBARRIER_INVAL(sb + SMO_MB + 8);
    }
}

// ---------------------------------------------------------------------------
// Tail kernel 1: reduce 64 partials -> doc (round-10 version: grid (8,32),
// warp lanes span 32 consecutive cols, SMEM combine — measured 6.0 us).
// ---------------------------------------------------------------------------
__global__ void reduce_kernel(const int* __restrict__ lengths)
{
    __shared__ float ss[8][64];
    __shared__ float sm[8][64];
    const int b    = blockIdx.y;
    const int cb   = blockIdx.x * 64;
    const int tid  = threadIdx.x;
    const int w    = tid >> 5;
    const int lane = tid & 31;

    int len = lengths[b];
    if (len < 1) len = 1;
    if (len > Tt) len = Tt;

    const float* ps = g_psum + (size_t)b * NPART * 512 + cb;
    const float* pm = g_pmax + (size_t)b * NPART * 512 + cb;

    float s0 = 0.f, s1 = 0.f, m0 = -1e30f, m1 = -1e30f;
#pragma unroll
    for (int k = 0; k < 8; k++) {
        const int p = w + k * 8;
        s0 += ps[p * 512 + lane];
        s1 += ps[p * 512 + 32 + lane];
        m0 = fmaxf(m0, pm[p * 512 + lane]);
        m1 = fmaxf(m1, pm[p * 512 + 32 + lane]);
    }
    ss[w][lane] = s0; ss[w][32 + lane] = s1;
    sm[w][lane] = m0; sm[w][32 + lane] = m1;
    __syncthreads();

    if (tid < 64) {
        float S = 0.f, M = -1e30f;
#pragma unroll
        for (int w2 = 0; w2 < 8; w2++) {
            S += ss[w2][tid];
            M = fmaxf(M, sm[w2][tid]);
        }
        g_doc[b * 1024 + cb + tid]       = fmaxf(S / (float)len, 0.0f);
        g_doc[b * 1024 + 512 + cb + tid] = fmaxf(M, 0.0f);
    }
}

// ---------------------------------------------------------------------------
// Tail kernel 2: layer 1, float4 W1 loads. Grid (8, 32).
// ---------------------------------------------------------------------------
__global__ void mlp1_kernel(const float* __restrict__ W1, const float* __restrict__ b1)
{
    __shared__ float4 doc[256];
    const int b   = blockIdx.y;
    const int og  = blockIdx.x;
    const int tid = threadIdx.x;
    const int wid = tid >> 5;
    const int lane = tid & 31;

    doc[tid] = *(const float4*)&g_doc[b * 1024 + tid * 4];
    __syncthreads();

    const int n0 = og * 32 + wid * 4;
    const float4* __restrict__ w0 = (const float4*)(W1 + (size_t)(n0 + 0) * 1024);
    const float4* __restrict__ w1 = (const float4*)(W1 + (size_t)(n0 + 1) * 1024);
    const float4* __restrict__ w2 = (const float4*)(W1 + (size_t)(n0 + 2) * 1024);
    const float4* __restrict__ w3 = (const float4*)(W1 + (size_t)(n0 + 3) * 1024);

    float s0 = 0.f, s1 = 0.f, s2 = 0.f, s3 = 0.f;
#pragma unroll
    for (int k4 = lane; k4 < 256; k4 += 32) {
        const float4 d = doc[k4];
        float4 a = w0[k4];
        s0 = fmaf(a.x, d.x, fmaf(a.y, d.y, fmaf(a.z, d.z, fmaf(a.w, d.w, s0))));
        a = w1[k4];
        s1 = fmaf(a.x, d.x, fmaf(a.y, d.y, fmaf(a.z, d.z, fmaf(a.w, d.w, s1))));
        a = w2[k4];
        s2 = fmaf(a.x, d.x, fmaf(a.y, d.y, fmaf(a.z, d.z, fmaf(a.w, d.w, s2))));
        a = w3[k4];
        s3 = fmaf(a.x, d.x, fmaf(a.y, d.y, fmaf(a.z, d.z, fmaf(a.w, d.w, s3))));
    }
#pragma unroll
    for (int off = 16; off > 0; off >>= 1) {
        s0 += __shfl_xor_sync(0xFFFFFFFFu, s0, off);
        s1 += __shfl_xor_sync(0xFFFFFFFFu, s1, off);
        s2 += __shfl_xor_sync(0xFFFFFFFFu, s2, off);
        s3 += __shfl_xor_sync(0xFFFFFFFFu, s3, off);
    }
    if (lane == 0) {
        g_d1[b * 256 + n0 + 0] = s0 + b1[n0 + 0];
        g_d1[b * 256 + n0 + 1] = s1 + b1[n0 + 1];
        g_d1[b * 256 + n0 + 2] = s2 + b1[n0 + 2];
        g_d1[b * 256 + n0 + 3] = s3 + b1[n0 + 3];
    }
}

// ---------------------------------------------------------------------------
// Tail kernel 3: layer 2, float4. Grid 32.
// ---------------------------------------------------------------------------
__global__ void mlp2_kernel(const float* __restrict__ W2, const float* __restrict__ b2,
                            float* __restrict__ out)
{
    __shared__ float4 d1s[64];
    const int b   = blockIdx.x;
    const int tid = threadIdx.x;
    const int wid = tid >> 5;
    const int lane = tid & 31;

    if (tid < 64) d1s[tid] = *(const float4*)&g_d1[b * 256 + tid * 4];
    __syncthreads();

    for (int m = wid; m < NLBL; m += 8) {
        const float4* __restrict__ w2r = (const float4*)(W2 + m * 256);
        float s = 0.0f;
#pragma unroll
        for (int k4 = lane; k4 < 64; k4 += 32) {
            const float4 d = d1s[k4];
            const float4 a = w2r[k4];
            s = fmaf(a.x, d.x, fmaf(a.y, d.y, fmaf(a.z, d.z, fmaf(a.w, d.w, s))));
        }
#pragma unroll
        for (int off = 16; off > 0; off >>= 1)
            s += __shfl_xor_sync(0xFFFFFFFFu, s, off);
        if (lane == 0) out[b * NLBL + m] = s + b2[m];
    }
}

// ---------------------------------------------------------------------------
extern "C" void kernel_launch(void* const* d_in, const int* in_sizes, int n_in,
                              void* d_out, int out_size)
{
    const float* X    = (const float*)d_in[0];
    const int*   lens = (const int*)  d_in[1];
    const float* Wf   = (const float*)d_in[2];
    const float* bihf = (const float*)d_in[3];
    const float* bhhf = (const float*)d_in[4];
    const float* Wr   = (const float*)d_in[5];
    const float* bihr = (const float*)d_in[6];
    const float* bhhr = (const float*)d_in[7];
    const float* W1   = (const float*)d_in[8];
    const float* b1   = (const float*)d_in[9];
    const float* W2   = (const float*)d_in[10];
    const float* b2   = (const float*)d_in[11];
    float* out = (float*)d_out;

    cudaFuncSetAttribute(gemm_mma_kernel, cudaFuncAttributeMaxDynamicSharedMemorySize, SMEM_GEMM);

    conv_x_kernel<<<8192, 256>>>(X, lens);
    conv_w_kernel<<<192, 256>>>(Wf, Wr);

    dim3 gG(4, 1024);
    gemm_mma_kernel<<<gG, 256, SMEM_GEMM>>>(lens, bihf, bhhf, bihr, bhhr);

    dim3 gR(8, Bb);
    reduce_kernel<<<gR, 256>>>(lens);
    dim3 gM1(8, Bb);
    mlp1_kernel<<<gM1, 256>>>(W1, b1);
    mlp2_kernel<<<Bb, 256>>>(W2, b2, out);
}

// round 14
// speedup vs baseline: 2.7452x; 1.0279x over previous
#include <cuda_runtime.h>
#include <cuda_bf16.h>
#include <math.h>
#include <stdint.h>

// Problem constants
#define Bb   32
#define Tt   2048
#define Ee   256
#define Hh   256
#define NLBL 20
#define Mrows (Bb * Tt)   // 65536
#define NPART 64          // 32-row pooling partials per batch (2048/32)

// ---------------------------------------------------------------------------
// Device scratch.
// g_X2s: per 64-row tile, 8 slabs of [64 rows x 128 B] (SW128 within row):
//   slab 2c = X hi chunk c ; slab 2c+1 = X lo chunk c
// g_W2s: per (dir,jq) quarter (8 images), 8 slabs of [192 rows x 128 B]:
//   slab c = W hi chunk c ; slab 4+c = W lo chunk c
//   row order GATE-INTERLEAVED at 16 cols: r3 = (jl>>4)*48 + gate*16 + (jl&15)
// ---------------------------------------------------------------------------
__device__ __align__(128) unsigned char g_X2s[(size_t)1024 * 8 * 8192];   // 64 MB
__device__ __align__(128) unsigned char g_W2s[(size_t)8 * 8 * 24576];     // 1.5 MB
__device__ float g_psum[Bb * NPART * 512];
__device__ float g_pmax[Bb * NPART * 512];
__device__ float g_doc[Bb * 1024];
__device__ float g_d1[Bb * 256];

// ---------------------------------------------------------------------------
// PTX helpers
// ---------------------------------------------------------------------------
__device__ __forceinline__ uint32_t smem_u32(const void* p) {
    uint32_t a;
    asm("{ .reg .u64 t; cvta.to.shared.u64 t, %1; cvt.u32.u64 %0, t; }" : "=r"(a) : "l"(p));
    return a;
}
__device__ __forceinline__ float tanha(float x) {
    float y;
    asm("tanh.approx.f32 %0, %1;" : "=f"(y) : "f"(x));
    return y;
}

#define MBARRIER_INIT(addr, cnt) \
    asm volatile("mbarrier.init.shared.b64 [%0], %1;" :: "r"((uint32_t)(addr)), "r"((uint32_t)(cnt)) : "memory")
#define MBARRIER_INVAL(addr) \
    asm volatile("mbarrier.inval.shared.b64 [%0];" :: "r"((uint32_t)(addr)) : "memory")
#define MBARRIER_EXPECT_TX(addr, bytes) \
    asm volatile("mbarrier.arrive.expect_tx.shared.b64 _, [%0], %1;" :: "r"((uint32_t)(addr)), "r"((uint32_t)(bytes)) : "memory")

#define MBARRIER_WAIT_PARITY(mbar_smem_addr, phase_parity) do { \
    uint32_t _mbar = (uint32_t)(mbar_smem_addr); \
    uint32_t _parity = (uint32_t)(phase_parity); \
    uint32_t _done; \
    asm volatile( \
        "{\n\t.reg .pred p;\n\t" \
        "mbarrier.try_wait.parity.acquire.cta.shared::cta.b64 p, [%1], %2;\n\t" \
        "selp.b32 %0, 1, 0, p;\n\t}" \
        : "=r"(_done) : "r"(_mbar), "r"(_parity) : "memory"); \
    if (!_done) { \
        asm volatile( \
            "{\n\t.reg .pred P1;\n\t" \
            "WAIT_LOOP_%=:\n\t" \
            "mbarrier.try_wait.parity.acquire.cta.shared::cta.b64 P1, [%0], %1, 0x989680;\n\t" \
            "@P1 bra.uni WAIT_DONE_%=;\n\t" \
            "bra.uni WAIT_LOOP_%=;\n\t" \
            "WAIT_DONE_%=:\n\t}" \
            :: "r"(_mbar), "r"(_parity) : "memory"); \
    } \
} while (0)

#define CP_BULK(dst, src, sz, mbar) \
    asm volatile("cp.async.bulk.shared::cluster.global.mbarrier::complete_tx::bytes [%0], [%1], %2, [%3];" \
                 :: "r"((uint32_t)(dst)), "l"(src), "r"((uint32_t)(sz)), "r"((uint32_t)(mbar)) : "memory")

#define LDSM_X4(r0, r1, r2, r3, addr) \
    asm volatile("ldmatrix.sync.aligned.m8n8.x4.shared.b16 {%0,%1,%2,%3}, [%4];" \
                 : "=r"(r0), "=r"(r1), "=r"(r2), "=r"(r3) : "r"(addr))

#define MMA_BF16(d, a, b0, b1) \
    asm volatile("mma.sync.aligned.m16n8k16.row.col.f32.bf16.bf16.f32 " \
                 "{%0,%1,%2,%3}, {%4,%5,%6,%7}, {%8,%9}, {%0,%1,%2,%3};" \
                 : "+f"((d)[0]), "+f"((d)[1]), "+f"((d)[2]), "+f"((d)[3]) \
                 : "r"((a)[0]), "r"((a)[1]), "r"((a)[2]), "r"((a)[3]), \
                   "r"(b0), "r"(b1))

__device__ __forceinline__ uint32_t sw128(uint32_t off) {
    return off ^ ((off >> 3) & 0x70);
}

__device__ __forceinline__ uint32_t pack2(unsigned short a, unsigned short b) {
    return (uint32_t)a | ((uint32_t)b << 16);
}

// ---------------------------------------------------------------------------
// Convert X -> pre-swizzled bf16 hi/lo slab images (unchanged). Grid 8192x256.
// ---------------------------------------------------------------------------
__global__ void conv_x_kernel(const float* __restrict__ X, const int* __restrict__ lengths) {
    size_t i = (size_t)blockIdx.x * 256 + threadIdx.x;
    size_t row = i >> 5;
    int m = (int)(i & 31);
    int b = (int)(row >> 11);
    int t = (int)(row & 2047);
    int len = lengths[b];
    if (len < 1) len = 1;
    if (len > Tt) len = Tt;
    if (t >= len) return;

    const float4* xp = reinterpret_cast<const float4*>(X + row * 256 + m * 8);
    float4 v0 = xp[0];
    float4 v1 = xp[1];
    float xs[8] = {v0.x, v0.y, v0.z, v0.w, v1.x, v1.y, v1.z, v1.w};
    unsigned short hi[8], lo[8];
#pragma unroll
    for (int j = 0; j < 8; j++) {
        __nv_bfloat16 h = __float2bfloat16(xs[j]);
        __nv_bfloat16 l = __float2bfloat16(xs[j] - __bfloat162float(h));
        hi[j] = __bfloat16_as_ushort(h);
        lo[j] = __bfloat16_as_ushort(l);
    }

    const int tile = (int)(row >> 6);
    const int r    = (int)(row & 63);
    const int c    = m >> 3;
    const int unit = (m & 7) ^ (r & 7);

    uint4 hv = make_uint4(pack2(hi[0], hi[1]), pack2(hi[2], hi[3]),
                          pack2(hi[4], hi[5]), pack2(hi[6], hi[7]));
    uint4 lv = make_uint4(pack2(lo[0], lo[1]), pack2(lo[2], lo[3]),
                          pack2(lo[4], lo[5]), pack2(lo[6], lo[7]));
    size_t hi_base = ((size_t)(tile * 8 + 2 * c) * 64 + r) * 128 + unit * 16;
    size_t lo_base = ((size_t)(tile * 8 + 2 * c + 1) * 64 + r) * 128 + unit * 16;
    *(uint4*)(g_X2s + hi_base) = hv;
    *(uint4*)(g_X2s + lo_base) = lv;
}

// Convert W -> pre-swizzled QUARTER images, gate-interleaved at 16 cols.
__global__ void conv_w_kernel(const float* __restrict__ Wf, const float* __restrict__ Wr) {
    int i = blockIdx.x * 256 + threadIdx.x;   // 49152 threads
    int n = i >> 5;                            // 0..1535
    int m = i & 31;
    int dir = n / 768;
    int rem = n - dir * 768;
    int gate = rem >> 8;
    int jj = rem & 255;
    int gr = (gate == 0) ? jj : (gate == 1) ? 512 + jj : 768 + jj;
    const float* W = dir ? Wr : Wf;
    const float4* wp = reinterpret_cast<const float4*>(W + (size_t)gr * 256 + m * 8);
    float4 v0 = wp[0];
    float4 v1 = wp[1];
    float xs[8] = {v0.x, v0.y, v0.z, v0.w, v1.x, v1.y, v1.z, v1.w};
    unsigned short hi[8], lo[8];
#pragma unroll
    for (int j = 0; j < 8; j++) {
        __nv_bfloat16 h = __float2bfloat16(xs[j]);
        __nv_bfloat16 l = __float2bfloat16(xs[j] - __bfloat162float(h));
        hi[j] = __bfloat16_as_ushort(h);
        lo[j] = __bfloat16_as_ushort(l);
    }

    const int jq  = jj >> 6;                 // quarter 0..3
    const int jl  = jj & 63;
    const int r3  = (jl >> 4) * 48 + gate * 16 + (jl & 15);   // 0..191
    const int c   = m >> 3;
    const int unit = (m & 7) ^ (r3 & 7);
    const int img  = (dir * 4 + jq) * 8;

    uint4 hv = make_uint4(pack2(hi[0], hi[1]), pack2(hi[2], hi[3]),
                          pack2(hi[4], hi[5]), pack2(hi[6], hi[7]));
    uint4 lv = make_uint4(pack2(lo[0], lo[1]), pack2(lo[2], lo[3]),
                          pack2(lo[4], lo[5]), pack2(lo[6], lo[7]));
    size_t hi_base = ((size_t)(img + c) * 192 + r3) * 128 + unit * 16;
    size_t lo_base = ((size_t)(img + 4 + c) * 192 + r3) * 128 + unit * 16;
    *(uint4*)(g_W2s + hi_base) = hv;
    *(uint4*)(g_W2s + lo_base) = lv;
}

// ---------------------------------------------------------------------------
// HMMA gates-GEMM, quarter-N tiles (64 h-cols/CTA), occupancy 3.
// Grid (8, 1024): x -> {dir, jq}, y -> 64-row M tile.
// Warp: warpM = (wid&1)*32, hb = wid>>1 -> 16 h-cols, warpN = hb*48.
// Warp's 48 N-cols = [i(16)|g(16)|o(16)].
// ---------------------------------------------------------------------------
#define SMA_SZ 8192
#define SMB_SZ 24576        // 192 rows * 128 B
#define SMO_B  16384
#define SMO_MB (SMO_B + 2 * SMB_SZ)     // 65536
#define SMEM_GEMM (SMO_MB + 64)          // 65600 -> 3 CTAs/SM by SMEM

__global__ __launch_bounds__(256, 3) void gemm_mma_kernel(
    const int* __restrict__ lengths,
    const float* __restrict__ bihf, const float* __restrict__ bhhf,
    const float* __restrict__ bihr, const float* __restrict__ bhhr)
{
    extern __shared__ char smem[];
    const uint32_t sb = smem_u32(smem);
    const int tid  = threadIdx.x;
    const int wid  = tid >> 5;
    const int lane = tid & 31;
    const int dir  = blockIdx.x >> 2;
    const int jq   = blockIdx.x & 3;
    const int rb   = blockIdx.y * 64;

    const int b      = rb >> 11;
    const int tstart = rb & 2047;
    int len = lengths[b];
    if (len < 1) len = 1;
    if (len > Tt) len = Tt;

    if (tstart >= len) {   // entire tile masked out: write zero partials (64 cols x 2 rows)
        if (tid < 128) {
            const int jj = tid & 63;
            const int rh = tid >> 6;
            const int pidx = ((b << 6) + (tstart >> 5) + rh) * 512 + dir * 256 + jq * 64 + jj;
            g_psum[pidx] = 0.0f;
            g_pmax[pidx] = -1e30f;
        }
        return;
    }

    const int warpM = (wid & 1) * 32;
    const int hb    = wid >> 1;            // 16-h-col group (0..3)
    const int warpN = hb * 48;

    const int tile8   = (rb >> 6) * 8;
    const int imgbase = (dir * 4 + jq) * 8;

    auto bload = [](int s) { return (s >= 8) || ((s & 1) == 0); };
    auto bbuff = [](int s) { return (s < 8) ? ((s >> 1) & 1) : (s & 1); };
    auto aslab = [](int s) { return (s < 8) ? s : 2 * (s - 8); };
    auto bslab = [](int s) { return (s < 8) ? (s >> 1) : 4 + (s - 8); };

    if (tid == 0) {
        MBARRIER_INIT(sb + SMO_MB, 1);
        MBARRIER_INIT(sb + SMO_MB + 8, 1);
    }
    __syncthreads();

    auto issue = [&](int s) {
        const uint32_t mb = sb + SMO_MB + ((s & 1) << 3);
        const uint32_t bytes = SMA_SZ + (bload(s) ? SMB_SZ : 0);
        MBARRIER_EXPECT_TX(mb, bytes);
        const unsigned char* asrc = g_X2s + (size_t)(tile8 + aslab(s)) * SMA_SZ;
        CP_BULK(sb + (s & 1) * SMA_SZ, asrc, SMA_SZ, mb);
        if (bload(s)) {
            const unsigned char* bsrc = g_W2s + (size_t)(imgbase + bslab(s)) * SMB_SZ;
            CP_BULK(sb + SMO_B + bbuff(s) * SMB_SZ, bsrc, SMB_SZ, mb);
        }
    };

    if (tid == 0) issue(0);

    float acc[2][6][4];
#pragma unroll
    for (int i = 0; i < 2; i++)
#pragma unroll
        for (int j = 0; j < 6; j++)
#pragma unroll
            for (int k = 0; k < 4; k++) acc[i][j][k] = 0.0f;

    const int aL_row = ((lane >> 3) & 1) * 8 + (lane & 7);
    const int aL_k   = (lane >> 4);
    const int bL_n   = (lane >> 4) * 8 + (lane & 7);
    const int bL_k   = (lane >> 3) & 1;

    for (int s = 0; s < 12; s++) {
        if (s < 11 && tid == 0) issue(s + 1);

        MBARRIER_WAIT_PARITY(sb + SMO_MB + ((s & 1) << 3), (s >> 1) & 1);

        const uint32_t sa = sb + (s & 1) * SMA_SZ;
        const uint32_t sB = sb + SMO_B + bbuff(s) * SMB_SZ;

#pragma unroll
        for (int kk = 0; kk < 4; kk++) {
            uint32_t afr[2][4];
#pragma unroll
            for (int sub = 0; sub < 2; sub++) {
                int row = warpM + sub * 16 + aL_row;
                uint32_t off = sw128((uint32_t)(row * 128 + (kk * 2 + aL_k) * 16));
                LDSM_X4(afr[sub][0], afr[sub][1], afr[sub][2], afr[sub][3], sa + off);
            }
#pragma unroll
            for (int p = 0; p < 3; p++) {
                uint32_t b0, b1, b2, b3;
                int n = warpN + p * 16 + bL_n;
                uint32_t off = sw128((uint32_t)(n * 128 + (kk * 2 + bL_k) * 16));
                LDSM_X4(b0, b1, b2, b3, sB + off);
                MMA_BF16(acc[0][2 * p],     afr[0], b0, b1);
                MMA_BF16(acc[0][2 * p + 1], afr[0], b2, b3);
                MMA_BF16(acc[1][2 * p],     afr[1], b0, b1);
                MMA_BF16(acc[1][2 * p + 1], afr[1], b2, b3);
            }
        }
        __syncthreads();
    }

    // register-level epilogue: tanh.approx activation + masked pooling.
    // Warp's 48 cols = [i: tiles 0-1 | g: tiles 2-3 | o: tiles 4-5].
    {
        const float* __restrict__ bih = dir ? bihr : bihf;
        const float* __restrict__ bhh = dir ? bhhr : bhhf;
        const int g  = lane >> 2;
        const int tg = lane & 3;

        const int vrw  = len - tstart - warpM;
        const int prow = (b << 6) + (tstart >> 5) + (wid & 1);
        const int pcb  = dir * 256 + jq * 64 + hb * 16;

        if (vrw <= 0) {
            if (lane < 4) {
#pragma unroll
                for (int q = 0; q < 2; q++)
#pragma unroll
                    for (int c = 0; c < 2; c++) {
                        const int pc = pcb + q * 8 + 2 * tg + c;
                        g_psum[prow * 512 + pc] = 0.0f;
                        g_pmax[prow * 512 + pc] = -1e30f;
                    }
            }
        } else {
            const bool v0 = (g)      < vrw;
            const bool v1 = (g + 8)  < vrw;
            const bool v2 = (g + 16) < vrw;
            const bool v3 = (g + 24) < vrw;
#pragma unroll
            for (int q = 0; q < 2; q++) {
#pragma unroll
                for (int c = 0; c < 2; c++) {
                    const int j = jq * 64 + hb * 16 + q * 8 + 2 * tg + c;   // within dir
                    const float Bi = bih[j]       + bhh[j];
                    const float Bg = bih[512 + j] + bhh[512 + j];
                    const float Bo = bih[768 + j] + bhh[768 + j];

                    float iv[4] = {acc[0][q][c],     acc[0][q][2 + c],
                                   acc[1][q][c],     acc[1][q][2 + c]};
                    float gv[4] = {acc[0][2 + q][c], acc[0][2 + q][2 + c],
                                   acc[1][2 + q][c], acc[1][2 + q][2 + c]};
                    float ov[4] = {acc[0][4 + q][c], acc[0][4 + q][2 + c],
                                   acc[1][4 + q][c], acc[1][4 + q][2 + c]};
                    const bool vld[4] = {v0, v1, v2, v3};

                    float s = 0.0f, m = -1e30f;
#pragma unroll
                    for (int r = 0; r < 4; r++) {
                        float si = fmaf(0.5f, tanha(0.5f * (iv[r] + Bi)), 0.5f);
                        float cs = si * tanha(gv[r] + Bg);
                        float so = fmaf(0.5f, tanha(0.5f * (ov[r] + Bo)), 0.5f);
                        float h  = so * tanha(cs);
                        if (vld[r]) { s += h; m = fmaxf(m, h); }
                    }
#pragma unroll
                    for (int off = 4; off < 32; off <<= 1) {
                        s += __shfl_xor_sync(0xFFFFFFFFu, s, off);
                        m = fmaxf(m, __shfl_xor_sync(0xFFFFFFFFu, m, off));
                    }
                    if (g == 0) {
                        const int pc = pcb + q * 8 + 2 * tg + c;
                        g_psum[prow * 512 + pc] = s;
                        g_pmax[prow * 512 + pc] = m;
                    }
                }
            }
        }
    }

    __syncthreads();
    if (tid == 0) {
        MBARRIER_INVAL(sb + SMO_MB);
        MBARRIER_INVAL(sb + SMO_MB + 8);
    }
}

// ---------------------------------------------------------------------------
// Tail kernel 1: reduce 64 partials -> doc (round-13 version, 6.5 us).
// ---------------------------------------------------------------------------
__global__ void reduce_kernel(const int* __restrict__ lengths)
{
    __shared__ float ss[8][64];
    __shared__ float sm[8][64];
    const int b    = blockIdx.y;
    const int cb   = blockIdx.x * 64;
    const int tid  = threadIdx.x;
    const int w    = tid >> 5;
    const int lane = tid & 31;

    int len = lengths[b];
    if (len < 1) len = 1;
    if (len > Tt) len = Tt;

    const float* ps = g_psum + (size_t)b * NPART * 512 + cb;
    const float* pm = g_pmax + (size_t)b * NPART * 512 + cb;

    float s0 = 0.f, s1 = 0.f, m0 = -1e30f, m1 = -1e30f;
#pragma unroll
    for (int k = 0; k < 8; k++) {
        const int p = w + k * 8;
        s0 += ps[p * 512 + lane];
        s1 += ps[p * 512 + 32 + lane];
        m0 = fmaxf(m0, pm[p * 512 + lane]);
        m1 = fmaxf(m1, pm[p * 512 + 32 + lane]);
    }
    ss[w][lane] = s0; ss[w][32 + lane] = s1;
    sm[w][lane] = m0; sm[w][32 + lane] = m1;
    __syncthreads();

    if (tid < 64) {
        float S = 0.f, M = -1e30f;
#pragma unroll
        for (int w2 = 0; w2 < 8; w2++) {
            S += ss[w2][tid];
            M = fmaxf(M, sm[w2][tid]);
        }
        g_doc[b * 1024 + cb + tid]       = fmaxf(S / (float)len, 0.0f);
        g_doc[b * 1024 + 512 + cb + tid] = fmaxf(M, 0.0f);
    }
}

// ---------------------------------------------------------------------------
// Tail kernel 2: layer 1, float4 W1 loads. Grid (8, 32).
// ---------------------------------------------------------------------------
__global__ void mlp1_kernel(const float* __restrict__ W1, const float* __restrict__ b1)
{
    __shared__ float4 doc[256];
    const int b   = blockIdx.y;
    const int og  = blockIdx.x;
    const int tid = threadIdx.x;
    const int wid = tid >> 5;
    const int lane = tid & 31;

    doc[tid] = *(const float4*)&g_doc[b * 1024 + tid * 4];
    __syncthreads();

    const int n0 = og * 32 + wid * 4;
    const float4* __restrict__ w0 = (const float4*)(W1 + (size_t)(n0 + 0) * 1024);
    const float4* __restrict__ w1 = (const float4*)(W1 + (size_t)(n0 + 1) * 1024);
    const float4* __restrict__ w2 = (const float4*)(W1 + (size_t)(n0 + 2) * 1024);
    const float4* __restrict__ w3 = (const float4*)(W1 + (size_t)(n0 + 3) * 1024);

    float s0 = 0.f, s1 = 0.f, s2 = 0.f, s3 = 0.f;
#pragma unroll
    for (int k4 = lane; k4 < 256; k4 += 32) {
        const float4 d = doc[k4];
        float4 a = w0[k4];
        s0 = fmaf(a.x, d.x, fmaf(a.y, d.y, fmaf(a.z, d.z, fmaf(a.w, d.w, s0))));
        a = w1[k4];
        s1 = fmaf(a.x, d.x, fmaf(a.y, d.y, fmaf(a.z, d.z, fmaf(a.w, d.w, s1))));
        a = w2[k4];
        s2 = fmaf(a.x, d.x, fmaf(a.y, d.y, fmaf(a.z, d.z, fmaf(a.w, d.w, s2))));
        a = w3[k4];
        s3 = fmaf(a.x, d.x, fmaf(a.y, d.y, fmaf(a.z, d.z, fmaf(a.w, d.w, s3))));
    }
#pragma unroll
    for (int off = 16; off > 0; off >>= 1) {
        s0 += __shfl_xor_sync(0xFFFFFFFFu, s0, off);
        s1 += __shfl_xor_sync(0xFFFFFFFFu, s1, off);
        s2 += __shfl_xor_sync(0xFFFFFFFFu, s2, off);
        s3 += __shfl_xor_sync(0xFFFFFFFFu, s3, off);
    }
    if (lane == 0) {
        g_d1[b * 256 + n0 + 0] = s0 + b1[n0 + 0];
        g_d1[b * 256 + n0 + 1] = s1 + b1[n0 + 1];
        g_d1[b * 256 + n0 + 2] = s2 + b1[n0 + 2];
        g_d1[b * 256 + n0 + 3] = s3 + b1[n0 + 3];
    }
}

// ---------------------------------------------------------------------------
// Tail kernel 3: layer 2, float4. Grid 32.
// ---------------------------------------------------------------------------
__global__ void mlp2_kernel(const float* __restrict__ W2, const float* __restrict__ b2,
                            float* __restrict__ out)
{
    __shared__ float4 d1s[64];
    const int b   = blockIdx.x;
    const int tid = threadIdx.x;
    const int wid = tid >> 5;
    const int lane = tid & 31;

    if (tid < 64) d1s[tid] = *(const float4*)&g_d1[b * 256 + tid * 4];
    __syncthreads();

    for (int m = wid; m < NLBL; m += 8) {
        const float4* __restrict__ w2r = (const float4*)(W2 + m * 256);
        float s = 0.0f;
#pragma unroll
        for (int k4 = lane; k4 < 64; k4 += 32) {
            const float4 d = d1s[k4];
            const float4 a = w2r[k4];
            s = fmaf(a.x, d.x, fmaf(a.y, d.y, fmaf(a.z, d.z, fmaf(a.w, d.w, s))));
        }
#pragma unroll
        for (int off = 16; off > 0; off >>= 1)
            s += __shfl_xor_sync(0xFFFFFFFFu, s, off);
        if (lane == 0) out[b * NLBL + m] = s + b2[m];
    }
}

// ---------------------------------------------------------------------------
extern "C" void kernel_launch(void* const* d_in, const int* in_sizes, int n_in,
                              void* d_out, int out_size)
{
    const float* X    = (const float*)d_in[0];
    const int*   lens = (const int*)  d_in[1];
    const float* Wf   = (const float*)d_in[2];
    const float* bihf = (const float*)d_in[3];
    const float* bhhf = (const float*)d_in[4];
    const float* Wr   = (const float*)d_in[5];
    const float* bihr = (const float*)d_in[6];
    const float* bhhr = (const float*)d_in[7];
    const float* W1   = (const float*)d_in[8];
    const float* b1   = (const float*)d_in[9];
    const float* W2   = (const float*)d_in[10];
    const float* b2   = (const float*)d_in[11];
    float* out = (float*)d_out;

    cudaFuncSetAttribute(gemm_mma_kernel, cudaFuncAttributeMaxDynamicSharedMemorySize, SMEM_GEMM);

    conv_x_kernel<<<8192, 256>>>(X, lens);
    conv_w_kernel<<<192, 256>>>(Wf, Wr);

    dim3 gG(8, 1024);
    gemm_mma_kernel<<<gG, 256, SMEM_GEMM>>>(lens, bihf, bhhf, bihr, bhhr);

    dim3 gR(8, Bb);
    reduce_kernel<<<gR, 256>>>(lens);
    dim3 gM1(8, Bb);
    mlp1_kernel<<<gM1, 256>>>(W1, b1);
    mlp2_kernel<<<Bb, 256>>>(W2, b2, out);
}

// round 15
// speedup vs baseline: 2.7606x; 1.0056x over previous
#include <cuda_runtime.h>
#include <cuda_bf16.h>
#include <math.h>
#include <stdint.h>

// Problem constants
#define Bb   32
#define Tt   2048
#define Ee   256
#define Hh   256
#define NLBL 20
#define Mrows (Bb * Tt)   // 65536
#define NPART 64          // 32-row pooling partials per batch (2048/32)

// ---------------------------------------------------------------------------
// Device scratch.
// g_X2s: per 64-row tile, 8 slabs of [64 rows x 128 B] (SW128 within row):
//   slab 2c = X hi chunk c ; slab 2c+1 = X lo chunk c
// g_W2s: per (dir,jq) quarter (8 images), 8 slabs of [192 rows x 128 B]:
//   slab c = W hi chunk c ; slab 4+c = W lo chunk c
//   row order GATE-INTERLEAVED at 16 cols: r3 = (jl>>4)*48 + gate*16 + (jl&15)
// ---------------------------------------------------------------------------
__device__ __align__(128) unsigned char g_X2s[(size_t)1024 * 8 * 8192];   // 64 MB
__device__ __align__(128) unsigned char g_W2s[(size_t)8 * 8 * 24576];     // 1.5 MB
__device__ float g_psum[Bb * NPART * 512];
__device__ float g_pmax[Bb * NPART * 512];
__device__ float g_doc[Bb * 1024];
__device__ float g_d1[Bb * 256];

// ---------------------------------------------------------------------------
// PTX helpers
// ---------------------------------------------------------------------------
__device__ __forceinline__ uint32_t smem_u32(const void* p) {
    uint32_t a;
    asm("{ .reg .u64 t; cvta.to.shared.u64 t, %1; cvt.u32.u64 %0, t; }" : "=r"(a) : "l"(p));
    return a;
}
__device__ __forceinline__ float tanha(float x) {
    float y;
    asm("tanh.approx.f32 %0, %1;" : "=f"(y) : "f"(x));
    return y;
}

#define MBARRIER_INIT(addr, cnt) \
    asm volatile("mbarrier.init.shared.b64 [%0], %1;" :: "r"((uint32_t)(addr)), "r"((uint32_t)(cnt)) : "memory")
#define MBARRIER_INVAL(addr) \
    asm volatile("mbarrier.inval.shared.b64 [%0];" :: "r"((uint32_t)(addr)) : "memory")
#define MBARRIER_EXPECT_TX(addr, bytes) \
    asm volatile("mbarrier.arrive.expect_tx.shared.b64 _, [%0], %1;" :: "r"((uint32_t)(addr)), "r"((uint32_t)(bytes)) : "memory")

#define MBARRIER_WAIT_PARITY(mbar_smem_addr, phase_parity) do { \
    uint32_t _mbar = (uint32_t)(mbar_smem_addr); \
    uint32_t _parity = (uint32_t)(phase_parity); \
    uint32_t _done; \
    asm volatile( \
        "{\n\t.reg .pred p;\n\t" \
        "mbarrier.try_wait.parity.acquire.cta.shared::cta.b64 p, [%1], %2;\n\t" \
        "selp.b32 %0, 1, 0, p;\n\t}" \
        : "=r"(_done) : "r"(_mbar), "r"(_parity) : "memory"); \
    if (!_done) { \
        asm volatile( \
            "{\n\t.reg .pred P1;\n\t" \
            "WAIT_LOOP_%=:\n\t" \
            "mbarrier.try_wait.parity.acquire.cta.shared::cta.b64 P1, [%0], %1, 0x989680;\n\t" \
            "@P1 bra.uni WAIT_DONE_%=;\n\t" \
            "bra.uni WAIT_LOOP_%=;\n\t" \
            "WAIT_DONE_%=:\n\t}" \
            :: "r"(_mbar), "r"(_parity) : "memory"); \
    } \
} while (0)

#define CP_BULK(dst, src, sz, mbar) \
    asm volatile("cp.async.bulk.shared::cluster.global.mbarrier::complete_tx::bytes [%0], [%1], %2, [%3];" \
                 :: "r"((uint32_t)(dst)), "l"(src), "r"((uint32_t)(sz)), "r"((uint32_t)(mbar)) : "memory")

#define LDSM_X4(r0, r1, r2, r3, addr) \
    asm volatile("ldmatrix.sync.aligned.m8n8.x4.shared.b16 {%0,%1,%2,%3}, [%4];" \
                 : "=r"(r0), "=r"(r1), "=r"(r2), "=r"(r3) : "r"(addr))

#define MMA_BF16(d, a, b0, b1) \
    asm volatile("mma.sync.aligned.m16n8k16.row.col.f32.bf16.bf16.f32 " \
                 "{%0,%1,%2,%3}, {%4,%5,%6,%7}, {%8,%9}, {%0,%1,%2,%3};" \
                 : "+f"((d)[0]), "+f"((d)[1]), "+f"((d)[2]), "+f"((d)[3]) \
                 : "r"((a)[0]), "r"((a)[1]), "r"((a)[2]), "r"((a)[3]), \
                   "r"(b0), "r"(b1))

__device__ __forceinline__ uint32_t sw128(uint32_t off) {
    return off ^ ((off >> 3) & 0x70);
}

__device__ __forceinline__ uint32_t pack2(unsigned short a, unsigned short b) {
    return (uint32_t)a | ((uint32_t)b << 16);
}

// ---------------------------------------------------------------------------
// Fused converter: blocks [0, 8192) convert X rows; blocks [8192, 8384)
// convert W (quarter images, gate-interleaved at 16 cols).
// ---------------------------------------------------------------------------
__global__ void conv_fused_kernel(const float* __restrict__ X,
                                  const int* __restrict__ lengths,
                                  const float* __restrict__ Wf,
                                  const float* __restrict__ Wr)
{
    if (blockIdx.x < 8192) {
        // ---- X path: one 16B swizzle unit per image per thread ----
        size_t i = (size_t)blockIdx.x * 256 + threadIdx.x;
        size_t row = i >> 5;
        int m = (int)(i & 31);
        int b = (int)(row >> 11);
        int t = (int)(row & 2047);
        // one length load per 32-thread group (same row), broadcast via shfl
        int len;
        {
            int l = 0;
            if ((threadIdx.x & 31) == 0) l = lengths[b];
            // rows within a warp may differ (32 threads = 1 row group exactly
            // when (i&31) spans one row): i>>5 is constant across the 32-thread
            // group only if threads are aligned; here tid 0..255 -> 8 rows per
            // block, each row = 32 consecutive threads = 1 warp. So lane 0's b
            // is the warp's b.
            len = __shfl_sync(0xFFFFFFFFu, l, 0);
        }
        if (len < 1) len = 1;
        if (len > Tt) len = Tt;
        if (t >= len) return;

        const float4* xp = reinterpret_cast<const float4*>(X + row * 256 + m * 8);
        float4 v0 = xp[0];
        float4 v1 = xp[1];
        float xs[8] = {v0.x, v0.y, v0.z, v0.w, v1.x, v1.y, v1.z, v1.w};
        unsigned short hi[8], lo[8];
#pragma unroll
        for (int j = 0; j < 8; j++) {
            __nv_bfloat16 h = __float2bfloat16(xs[j]);
            __nv_bfloat16 l = __float2bfloat16(xs[j] - __bfloat162float(h));
            hi[j] = __bfloat16_as_ushort(h);
            lo[j] = __bfloat16_as_ushort(l);
        }

        const int tile = (int)(row >> 6);
        const int r    = (int)(row & 63);
        const int c    = m >> 3;
        const int unit = (m & 7) ^ (r & 7);

        uint4 hv = make_uint4(pack2(hi[0], hi[1]), pack2(hi[2], hi[3]),
                              pack2(hi[4], hi[5]), pack2(hi[6], hi[7]));
        uint4 lv = make_uint4(pack2(lo[0], lo[1]), pack2(lo[2], lo[3]),
                              pack2(lo[4], lo[5]), pack2(lo[6], lo[7]));
        size_t hi_base = ((size_t)(tile * 8 + 2 * c) * 64 + r) * 128 + unit * 16;
        size_t lo_base = ((size_t)(tile * 8 + 2 * c + 1) * 64 + r) * 128 + unit * 16;
        *(uint4*)(g_X2s + hi_base) = hv;
        *(uint4*)(g_X2s + lo_base) = lv;
    } else {
        // ---- W path ----
        int i = (blockIdx.x - 8192) * 256 + threadIdx.x;   // 49152 threads
        int n = i >> 5;                                     // 0..1535
        int m = i & 31;
        int dir = n / 768;
        int rem = n - dir * 768;
        int gate = rem >> 8;
        int jj = rem & 255;
        int gr = (gate == 0) ? jj : (gate == 1) ? 512 + jj : 768 + jj;
        const float* W = dir ? Wr : Wf;
        const float4* wp = reinterpret_cast<const float4*>(W + (size_t)gr * 256 + m * 8);
        float4 v0 = wp[0];
        float4 v1 = wp[1];
        float xs[8] = {v0.x, v0.y, v0.z, v0.w, v1.x, v1.y, v1.z, v1.w};
        unsigned short hi[8], lo[8];
#pragma unroll
        for (int j = 0; j < 8; j++) {
            __nv_bfloat16 h = __float2bfloat16(xs[j]);
            __nv_bfloat16 l = __float2bfloat16(xs[j] - __bfloat162float(h));
            hi[j] = __bfloat16_as_ushort(h);
            lo[j] = __bfloat16_as_ushort(l);
        }

        const int jq  = jj >> 6;
        const int jl  = jj & 63;
        const int r3  = (jl >> 4) * 48 + gate * 16 + (jl & 15);
        const int c   = m >> 3;
        const int unit = (m & 7) ^ (r3 & 7);
        const int img  = (dir * 4 + jq) * 8;

        uint4 hv = make_uint4(pack2(hi[0], hi[1]), pack2(hi[2], hi[3]),
                              pack2(hi[4], hi[5]), pack2(hi[6], hi[7]));
        uint4 lv = make_uint4(pack2(lo[0], lo[1]), pack2(lo[2], lo[3]),
                              pack2(lo[4], lo[5]), pack2(lo[6], lo[7]));
        size_t hi_base = ((size_t)(img + c) * 192 + r3) * 128 + unit * 16;
        size_t lo_base = ((size_t)(img + 4 + c) * 192 + r3) * 128 + unit * 16;
        *(uint4*)(g_W2s + hi_base) = hv;
        *(uint4*)(g_W2s + lo_base) = lv;
    }
}

// ---------------------------------------------------------------------------
// HMMA gates-GEMM, quarter-N tiles (64 h-cols/CTA), occupancy 3 (round 14).
// ---------------------------------------------------------------------------
#define SMA_SZ 8192
#define SMB_SZ 24576        // 192 rows * 128 B
#define SMO_B  16384
#define SMO_MB (SMO_B + 2 * SMB_SZ)     // 65536
#define SMEM_GEMM (SMO_MB + 64)          // 65600 -> 3 CTAs/SM by SMEM

__global__ __launch_bounds__(256, 3) void gemm_mma_kernel(
    const int* __restrict__ lengths,
    const float* __restrict__ bihf, const float* __restrict__ bhhf,
    const float* __restrict__ bihr, const float* __restrict__ bhhr)
{
    extern __shared__ char smem[];
    const uint32_t sb = smem_u32(smem);
    const int tid  = threadIdx.x;
    const int wid  = tid >> 5;
    const int lane = tid & 31;
    const int dir  = blockIdx.x >> 2;
    const int jq   = blockIdx.x & 3;
    const int rb   = blockIdx.y * 64;

    const int b      = rb >> 11;
    const int tstart = rb & 2047;
    int len = lengths[b];
    if (len < 1) len = 1;
    if (len > Tt) len = Tt;

    if (tstart >= len) {
        if (tid < 128) {
            const int jj = tid & 63;
            const int rh = tid >> 6;
            const int pidx = ((b << 6) + (tstart >> 5) + rh) * 512 + dir * 256 + jq * 64 + jj;
            g_psum[pidx] = 0.0f;
            g_pmax[pidx] = -1e30f;
        }
        return;
    }

    const int warpM = (wid & 1) * 32;
    const int hb    = wid >> 1;
    const int warpN = hb * 48;

    const int tile8   = (rb >> 6) * 8;
    const int imgbase = (dir * 4 + jq) * 8;

    auto bload = [](int s) { return (s >= 8) || ((s & 1) == 0); };
    auto bbuff = [](int s) { return (s < 8) ? ((s >> 1) & 1) : (s & 1); };
    auto aslab = [](int s) { return (s < 8) ? s : 2 * (s - 8); };
    auto bslab = [](int s) { return (s < 8) ? (s >> 1) : 4 + (s - 8); };

    if (tid == 0) {
        MBARRIER_INIT(sb + SMO_MB, 1);
        MBARRIER_INIT(sb + SMO_MB + 8, 1);
    }
    __syncthreads();

    auto issue = [&](int s) {
        const uint32_t mb = sb + SMO_MB + ((s & 1) << 3);
        const uint32_t bytes = SMA_SZ + (bload(s) ? SMB_SZ : 0);
        MBARRIER_EXPECT_TX(mb, bytes);
        const unsigned char* asrc = g_X2s + (size_t)(tile8 + aslab(s)) * SMA_SZ;
        CP_BULK(sb + (s & 1) * SMA_SZ, asrc, SMA_SZ, mb);
        if (bload(s)) {
            const unsigned char* bsrc = g_W2s + (size_t)(imgbase + bslab(s)) * SMB_SZ;
            CP_BULK(sb + SMO_B + bbuff(s) * SMB_SZ, bsrc, SMB_SZ, mb);
        }
    };

    if (tid == 0) issue(0);

    float acc[2][6][4];
#pragma unroll
    for (int i = 0; i < 2; i++)
#pragma unroll
        for (int j = 0; j < 6; j++)
#pragma unroll
            for (int k = 0; k < 4; k++) acc[i][j][k] = 0.0f;

    const int aL_row = ((lane >> 3) & 1) * 8 + (lane & 7);
    const int aL_k   = (lane >> 4);
    const int bL_n   = (lane >> 4) * 8 + (lane & 7);
    const int bL_k   = (lane >> 3) & 1;

    for (int s = 0; s < 12; s++) {
        if (s < 11 && tid == 0) issue(s + 1);

        MBARRIER_WAIT_PARITY(sb + SMO_MB + ((s & 1) << 3), (s >> 1) & 1);

        const uint32_t sa = sb + (s & 1) * SMA_SZ;
        const uint32_t sB = sb + SMO_B + bbuff(s) * SMB_SZ;

#pragma unroll
        for (int kk = 0; kk < 4; kk++) {
            uint32_t afr[2][4];
#pragma unroll
            for (int sub = 0; sub < 2; sub++) {
                int row = warpM + sub * 16 + aL_row;
                uint32_t off = sw128((uint32_t)(row * 128 + (kk * 2 + aL_k) * 16));
                LDSM_X4(afr[sub][0], afr[sub][1], afr[sub][2], afr[sub][3], sa + off);
            }
#pragma unroll
            for (int p = 0; p < 3; p++) {
                uint32_t b0, b1, b2, b3;
                int n = warpN + p * 16 + bL_n;
                uint32_t off = sw128((uint32_t)(n * 128 + (kk * 2 + bL_k) * 16));
                LDSM_X4(b0, b1, b2, b3, sB + off);
                MMA_BF16(acc[0][2 * p],     afr[0], b0, b1);
                MMA_BF16(acc[0][2 * p + 1], afr[0], b2, b3);
                MMA_BF16(acc[1][2 * p],     afr[1], b0, b1);
                MMA_BF16(acc[1][2 * p + 1], afr[1], b2, b3);
            }
        }
        __syncthreads();
    }

    // register-level epilogue: tanh.approx activation + masked pooling.
    {
        const float* __restrict__ bih = dir ? bihr : bihf;
        const float* __restrict__ bhh = dir ? bhhr : bhhf;
        const int g  = lane >> 2;
        const int tg = lane & 3;

        const int vrw  = len - tstart - warpM;
        const int prow = (b << 6) + (tstart >> 5) + (wid & 1);
        const int pcb  = dir * 256 + jq * 64 + hb * 16;

        if (vrw <= 0) {
            if (lane < 4) {
#pragma unroll
                for (int q = 0; q < 2; q++)
#pragma unroll
                    for (int c = 0; c < 2; c++) {
                        const int pc = pcb + q * 8 + 2 * tg + c;
                        g_psum[prow * 512 + pc] = 0.0f;
                        g_pmax[prow * 512 + pc] = -1e30f;
                    }
            }
        } else {
            const bool v0 = (g)      < vrw;
            const bool v1 = (g + 8)  < vrw;
            const bool v2 = (g + 16) < vrw;
            const bool v3 = (g + 24) < vrw;
#pragma unroll
            for (int q = 0; q < 2; q++) {
#pragma unroll
                for (int c = 0; c < 2; c++) {
                    const int j = jq * 64 + hb * 16 + q * 8 + 2 * tg + c;
                    const float Bi = bih[j]       + bhh[j];
                    const float Bg = bih[512 + j] + bhh[512 + j];
                    const float Bo = bih[768 + j] + bhh[768 + j];

                    float iv[4] = {acc[0][q][c],     acc[0][q][2 + c],
                                   acc[1][q][c],     acc[1][q][2 + c]};
                    float gv[4] = {acc[0][2 + q][c], acc[0][2 + q][2 + c],
                                   acc[1][2 + q][c], acc[1][2 + q][2 + c]};
                    float ov[4] = {acc[0][4 + q][c], acc[0][4 + q][2 + c],
                                   acc[1][4 + q][c], acc[1][4 + q][2 + c]};
                    const bool vld[4] = {v0, v1, v2, v3};

                    float s = 0.0f, m = -1e30f;
#pragma unroll
                    for (int r = 0; r < 4; r++) {
                        float si = fmaf(0.5f, tanha(0.5f * (iv[r] + Bi)), 0.5f);
                        float cs = si * tanha(gv[r] + Bg);
                        float so = fmaf(0.5f, tanha(0.5f * (ov[r] + Bo)), 0.5f);
                        float h  = so * tanha(cs);
                        if (vld[r]) { s += h; m = fmaxf(m, h); }
                    }
#pragma unroll
                    for (int off = 4; off < 32; off <<= 1) {
                        s += __shfl_xor_sync(0xFFFFFFFFu, s, off);
                        m = fmaxf(m, __shfl_xor_sync(0xFFFFFFFFu, m, off));
                    }
                    if (g == 0) {
                        const int pc = pcb + q * 8 + 2 * tg + c;
                        g_psum[prow * 512 + pc] = s;
                        g_pmax[prow * 512 + pc] = m;
                    }
                }
            }
        }
    }

    __syncthreads();
    if (tid == 0) {
        MBARRIER_INVAL(sb + SMO_MB);
        MBARRIER_INVAL(sb + SMO_MB + 8);
    }
}

// ---------------------------------------------------------------------------
// Tail kernel 1: reduce 64 partials -> doc (round-13 version).
// ---------------------------------------------------------------------------
__global__ void reduce_kernel(const int* __restrict__ lengths)
{
    __shared__ float ss[8][64];
    __shared__ float sm[8][64];
    const int b    = blockIdx.y;
    const int cb   = blockIdx.x * 64;
    const int tid  = threadIdx.x;
    const int w    = tid >> 5;
    const int lane = tid & 31;

    int len = lengths[b];
    if (len < 1) len = 1;
    if (len > Tt) len = Tt;

    const float* ps = g_psum + (size_t)b * NPART * 512 + cb;
    const float* pm = g_pmax + (size_t)b * NPART * 512 + cb;

    float s0 = 0.f, s1 = 0.f, m0 = -1e30f, m1 = -1e30f;
#pragma unroll
    for (int k = 0; k < 8; k++) {
        const int p = w + k * 8;
        s0 += ps[p * 512 + lane];
        s1 += ps[p * 512 + 32 + lane];
        m0 = fmaxf(m0, pm[p * 512 + lane]);
        m1 = fmaxf(m1, pm[p * 512 + 32 + lane]);
    }
    ss[w][lane] = s0; ss[w][32 + lane] = s1;
    sm[w][lane] = m0; sm[w][32 + lane] = m1;
    __syncthreads();

    if (tid < 64) {
        float S = 0.f, M = -1e30f;
#pragma unroll
        for (int w2 = 0; w2 < 8; w2++) {
            S += ss[w2][tid];
            M = fmaxf(M, sm[w2][tid]);
        }
        g_doc[b * 1024 + cb + tid]       = fmaxf(S / (float)len, 0.0f);
        g_doc[b * 1024 + 512 + cb + tid] = fmaxf(M, 0.0f);
    }
}

// ---------------------------------------------------------------------------
// Tail kernel 2: layer 1, float4 W1 loads. Grid (8, 32).
// ---------------------------------------------------------------------------
__global__ void mlp1_kernel(const float* __restrict__ W1, const float* __restrict__ b1)
{
    __shared__ float4 doc[256];
    const int b   = blockIdx.y;
    const int og  = blockIdx.x;
    const int tid = threadIdx.x;
    const int wid = tid >> 5;
    const int lane = tid & 31;

    doc[tid] = *(const float4*)&g_doc[b * 1024 + tid * 4];
    __syncthreads();

    const int n0 = og * 32 + wid * 4;
    const float4* __restrict__ w0 = (const float4*)(W1 + (size_t)(n0 + 0) * 1024);
    const float4* __restrict__ w1 = (const float4*)(W1 + (size_t)(n0 + 1) * 1024);
    const float4* __restrict__ w2 = (const float4*)(W1 + (size_t)(n0 + 2) * 1024);
    const float4* __restrict__ w3 = (const float4*)(W1 + (size_t)(n0 + 3) * 1024);

    float s0 = 0.f, s1 = 0.f, s2 = 0.f, s3 = 0.f;
#pragma unroll
    for (int k4 = lane; k4 < 256; k4 += 32) {
        const float4 d = doc[k4];
        float4 a = w0[k4];
        s0 = fmaf(a.x, d.x, fmaf(a.y, d.y, fmaf(a.z, d.z, fmaf(a.w, d.w, s0))));
        a = w1[k4];
        s1 = fmaf(a.x, d.x, fmaf(a.y, d.y, fmaf(a.z, d.z, fmaf(a.w, d.w, s1))));
        a = w2[k4];
        s2 = fmaf(a.x, d.x, fmaf(a.y, d.y, fmaf(a.z, d.z, fmaf(a.w, d.w, s2))));
        a = w3[k4];
        s3 = fmaf(a.x, d.x, fmaf(a.y, d.y, fmaf(a.z, d.z, fmaf(a.w, d.w, s3))));
    }
#pragma unroll
    for (int off = 16; off > 0; off >>= 1) {
        s0 += __shfl_xor_sync(0xFFFFFFFFu, s0, off);
        s1 += __shfl_xor_sync(0xFFFFFFFFu, s1, off);
        s2 += __shfl_xor_sync(0xFFFFFFFFu, s2, off);
        s3 += __shfl_xor_sync(0xFFFFFFFFu, s3, off);
    }
    if (lane == 0) {
        g_d1[b * 256 + n0 + 0] = s0 + b1[n0 + 0];
        g_d1[b * 256 + n0 + 1] = s1 + b1[n0 + 1];
        g_d1[b * 256 + n0 + 2] = s2 + b1[n0 + 2];
        g_d1[b * 256 + n0 + 3] = s3 + b1[n0 + 3];
    }
}

// ---------------------------------------------------------------------------
// Tail kernel 3: layer 2, float4. Grid 32.
// ---------------------------------------------------------------------------
__global__ void mlp2_kernel(const float* __restrict__ W2, const float* __restrict__ b2,
                            float* __restrict__ out)
{
    __shared__ float4 d1s[64];
    const int b   = blockIdx.x;
    const int tid = threadIdx.x;
    const int wid = tid >> 5;
    const int lane = tid & 31;

    if (tid < 64) d1s[tid] = *(const float4*)&g_d1[b * 256 + tid * 4];
    __syncthreads();

    for (int m = wid; m < NLBL; m += 8) {
        const float4* __restrict__ w2r = (const float4*)(W2 + m * 256);
        float s = 0.0f;
#pragma unroll
        for (int k4 = lane; k4 < 64; k4 += 32) {
            const float4 d = d1s[k4];
            const float4 a = w2r[k4];
            s = fmaf(a.x, d.x, fmaf(a.y, d.y, fmaf(a.z, d.z, fmaf(a.w, d.w, s))));
        }
#pragma unroll
        for (int off = 16; off > 0; off >>= 1)
            s += __shfl_xor_sync(0xFFFFFFFFu, s, off);
        if (lane == 0) out[b * NLBL + m] = s + b2[m];
    }
}

// ---------------------------------------------------------------------------
extern "C" void kernel_launch(void* const* d_in, const int* in_sizes, int n_in,
                              void* d_out, int out_size)
{
    const float* X    = (const float*)d_in[0];
    const int*   lens = (const int*)  d_in[1];
    const float* Wf   = (const float*)d_in[2];
    const float* bihf = (const float*)d_in[3];
    const float* bhhf = (const float*)d_in[4];
    const float* Wr   = (const float*)d_in[5];
    const float* bihr = (const float*)d_in[6];
    const float* bhhr = (const float*)d_in[7];
    const float* W1   = (const float*)d_in[8];
    const float* b1   = (const float*)d_in[9];
    const float* W2   = (const float*)d_in[10];
    const float* b2   = (const float*)d_in[11];
    float* out = (float*)d_out;

    cudaFuncSetAttribute(gemm_mma_kernel, cudaFuncAttributeMaxDynamicSharedMemorySize, SMEM_GEMM);

    conv_fused_kernel<<<8384, 256>>>(X, lens, Wf, Wr);

    dim3 gG(8, 1024);
    gemm_mma_kernel<<<gG, 256, SMEM_GEMM>>>(lens, bihf, bhhf, bihr, bhhr);

    dim3 gR(8, Bb);
    reduce_kernel<<<gR, 256>>>(lens);
    dim3 gM1(8, Bb);
    mlp1_kernel<<<gM1, 256>>>(W1, b1);
    mlp2_kernel<<<Bb, 256>>>(W2, b2, out);
}